// round 4
// baseline (speedup 1.0000x reference)
#include <cuda_runtime.h>
#include <math.h>
#include <stdint.h>

#define NN   20000
#define EE   320000
#define FIN  518
#define KPAD 528
#define DD   128
#define EDIM 32
#define HH   4
#define RR   26
#define HID  256
#define SCANB ((NN + 127) / 128)

// ---------------- scratch ----------------
__device__ float g_xp[(size_t)NN * KPAD];
__device__ float g_h1[(size_t)NN * HID];
__device__ float g_x[(size_t)NN * DD];
__device__ float g_hH[(size_t)NN * HH * DD];
__device__ float g_asd[NN * 2 * HH];              // interleaved: [n][0..3]=a_s, [n][4..7]=a_d
__device__ float g_alpha[(size_t)EE * HH];
__device__ float g_tab[2][RR][HH];                // per-layer relation-type attention table
__device__ int   g_deg[NN + 1];
__device__ int   g_off[NN + 1];
__device__ int   g_cur[NN];
__device__ int   g_eid[EE];
__device__ int   g_bsum[SCANB];

// ---------------- setup ----------------
__global__ void zero_deg() {
    int i = blockIdx.x * blockDim.x + threadIdx.x;
    if (i <= NN) g_deg[i] = 0;
}

__global__ void count_deg(const int* __restrict__ dst) {
    int e = blockIdx.x * blockDim.x + threadIdx.x;
    if (e < EE) atomicAdd(&g_deg[dst[e]], 1);
}

__global__ void scan_k1() {
    int i = blockIdx.x * 128 + threadIdx.x;
    int v = (i < NN) ? g_deg[i] : 0;
#pragma unroll
    for (int o = 16; o; o >>= 1) v += __shfl_xor_sync(0xffffffffu, v, o);
    __shared__ int sm[4];
    if ((threadIdx.x & 31) == 0) sm[threadIdx.x >> 5] = v;
    __syncthreads();
    if (threadIdx.x == 0) g_bsum[blockIdx.x] = sm[0] + sm[1] + sm[2] + sm[3];
}

__global__ void scan_k2() {   // 1 block, 256 threads
    __shared__ int s[256];
    int tid = threadIdx.x;
    int v = (tid < SCANB) ? g_bsum[tid] : 0;
    s[tid] = v;
    __syncthreads();
    for (int o = 1; o < 256; o <<= 1) {
        int t = (tid >= o) ? s[tid - o] : 0;
        __syncthreads();
        s[tid] += t;
        __syncthreads();
    }
    if (tid < SCANB) g_bsum[tid] = s[tid] - v;   // exclusive
}

__global__ void scan_k3() {
    int tid = threadIdx.x;
    int i = blockIdx.x * 128 + tid;
    int lane = tid & 31, warp = tid >> 5;
    int v = (i < NN) ? g_deg[i] : 0;
    int incl = v;
#pragma unroll
    for (int o = 1; o < 32; o <<= 1) {
        int n = __shfl_up_sync(0xffffffffu, incl, o);
        if (lane >= o) incl += n;
    }
    __shared__ int ws[4];
    if (lane == 31) ws[warp] = incl;
    __syncthreads();
    int wbase = 0;
    for (int w = 0; w < warp; w++) wbase += ws[w];
    int excl = g_bsum[blockIdx.x] + wbase + incl - v;
    if (i < NN) {
        g_off[i] = excl;
        g_cur[i] = excl;
        if (i == NN - 1) g_off[NN] = excl + v;
    }
}

__global__ void scatter_csr(const int* __restrict__ dst) {
    int e = blockIdx.x * blockDim.x + threadIdx.x;
    if (e >= EE) return;
    int pos = atomicAdd(&g_cur[dst[e]], 1);
    g_eid[pos] = e;
}

__global__ void pad_x(const float* __restrict__ x) {
    size_t i = blockIdx.x * (size_t)blockDim.x + threadIdx.x;
    if (i >= (size_t)NN * KPAD) return;
    int n = (int)(i / KPAD), c = (int)(i % KPAD);
    g_xp[i] = (c < FIN) ? x[(size_t)n * FIN + c] : 0.0f;
}

// tab[L][r][h] = sum_c rel[r,c] * (sum_d line_L[c, h*D+d] * atte_L[h,d])
__global__ void compute_tab(const float* __restrict__ rel,
                            const float* __restrict__ line0, const float* __restrict__ atte0,
                            const float* __restrict__ line1, const float* __restrict__ atte1) {
    __shared__ float we[2][HH][EDIM];
    int tid = threadIdx.x;    // 256
    if (tid < 2 * HH * EDIM) {
        int L = tid >> 7, rem = tid & 127;
        int h = rem / EDIM, c = rem % EDIM;
        const float* line = L ? line1 : line0;
        const float* atte = L ? atte1 : atte0;
        float s = 0.0f;
        for (int d = 0; d < DD; d++)
            s += line[(size_t)c * (HH * DD) + h * DD + d] * atte[h * DD + d];
        we[L][h][c] = s;
    }
    __syncthreads();
    if (tid < 2 * RR * HH) {
        int L = tid / (RR * HH), rem = tid % (RR * HH);
        int r = rem / HH, h = rem % HH;
        float s = 0.0f;
        for (int c = 0; c < EDIM; c++)
            s += rel[r * EDIM + c] * we[L][h][c];
        g_tab[L][r][h] = s;
    }
}

// ---------------- tf32 tensor-core GEMM (1xTF32) ----------------
__device__ __forceinline__ float to_tf32(float v) {
    uint32_t h;
    asm("cvt.rna.tf32.f32 %0, %1;" : "=r"(h) : "f"(v));
    return __uint_as_float(h);
}

__device__ __forceinline__ void mma8(float* c, const uint32_t* a, uint32_t b0, uint32_t b1) {
    asm volatile(
        "mma.sync.aligned.m16n8k8.row.col.f32.tf32.tf32.f32 "
        "{%0,%1,%2,%3}, {%4,%5,%6,%7}, {%8,%9}, {%0,%1,%2,%3};\n"
        : "+f"(c[0]), "+f"(c[1]), "+f"(c[2]), "+f"(c[3])
        : "r"(a[0]), "r"(a[1]), "r"(a[2]), "r"(a[3]), "r"(b0), "r"(b1));
}

__global__ __launch_bounds__(256, 2)
void mma_gemm(const float* __restrict__ A, const float* __restrict__ B,
              const float* __restrict__ bias, float* __restrict__ C,
              int M, int K, int KB, int Nn, int doRelu) {
    __shared__ float As[2][16][136];
    __shared__ float Bs[2][16][136];
    const int tid = threadIdx.x;
    const int warp = tid >> 5, lane = tid & 31;
    const int g = lane >> 2, tg = lane & 3;
    const int warpM = warp >> 1, warpN = warp & 1;     // 4 x 2 warps, warp tile 32x64
    const int rowBase = blockIdx.y * 128, colBase = blockIdx.x * 128;

    const int arow = tid >> 1, acol = (tid & 1) * 8;
    const int brow = tid >> 4, bcol = (tid & 15) * 8;

    float acc[2][8][4];
#pragma unroll
    for (int mi = 0; mi < 2; mi++)
#pragma unroll
        for (int ni = 0; ni < 8; ni++)
#pragma unroll
            for (int r = 0; r < 4; r++) acc[mi][ni][r] = 0.0f;

    const int nk = K / 16;

#define LOAD_TILES(BUF, K0)                                                       \
    {                                                                             \
        int grow = rowBase + arow;                                                \
        _Pragma("unroll")                                                         \
        for (int h = 0; h < 2; h++) {                                             \
            float4 v = make_float4(0.f, 0.f, 0.f, 0.f);                           \
            if (grow < M) v = *(const float4*)(A + (size_t)grow * K + (K0) + acol + h * 4); \
            As[BUF][acol + h * 4 + 0][arow] = to_tf32(v.x);                       \
            As[BUF][acol + h * 4 + 1][arow] = to_tf32(v.y);                       \
            As[BUF][acol + h * 4 + 2][arow] = to_tf32(v.z);                       \
            As[BUF][acol + h * 4 + 3][arow] = to_tf32(v.w);                       \
        }                                                                         \
        int kr = (K0) + brow;                                                     \
        _Pragma("unroll")                                                         \
        for (int h = 0; h < 2; h++) {                                             \
            float4 v = make_float4(0.f, 0.f, 0.f, 0.f);                           \
            if (kr < KB) v = *(const float4*)(B + (size_t)kr * Nn + colBase + bcol + h * 4); \
            v.x = to_tf32(v.x); v.y = to_tf32(v.y);                               \
            v.z = to_tf32(v.z); v.w = to_tf32(v.w);                               \
            *(float4*)&Bs[BUF][brow][bcol + h * 4] = v;                           \
        }                                                                         \
    }

    LOAD_TILES(0, 0)
    __syncthreads();

    for (int t = 0; t < nk; t++) {
        int buf = t & 1;
        if (t + 1 < nk) LOAD_TILES(buf ^ 1, (t + 1) * 16)

#pragma unroll
        for (int ks = 0; ks < 16; ks += 8) {
            uint32_t a[2][4];
#pragma unroll
            for (int mi = 0; mi < 2; mi++) {
                int mb = warpM * 32 + mi * 16 + g;
                a[mi][0] = __float_as_uint(As[buf][ks + tg][mb]);
                a[mi][1] = __float_as_uint(As[buf][ks + tg][mb + 8]);
                a[mi][2] = __float_as_uint(As[buf][ks + tg + 4][mb]);
                a[mi][3] = __float_as_uint(As[buf][ks + tg + 4][mb + 8]);
            }
#pragma unroll
            for (int ni = 0; ni < 8; ni++) {
                int nb = warpN * 64 + ni * 8 + g;
                uint32_t b0 = __float_as_uint(Bs[buf][ks + tg][nb]);
                uint32_t b1 = __float_as_uint(Bs[buf][ks + tg + 4][nb]);
#pragma unroll
                for (int mi = 0; mi < 2; mi++)
                    mma8(acc[mi][ni], a[mi], b0, b1);
            }
        }
        __syncthreads();
    }

#pragma unroll
    for (int mi = 0; mi < 2; mi++) {
        int r0 = rowBase + warpM * 32 + mi * 16 + g;
#pragma unroll
        for (int ni = 0; ni < 8; ni++) {
            int c0 = colBase + warpN * 64 + ni * 8 + tg * 2;
            float bb0 = bias ? bias[c0] : 0.0f;
            float bb1 = bias ? bias[c0 + 1] : 0.0f;
            if (r0 < M) {
                float v0 = acc[mi][ni][0] + bb0;
                float v1 = acc[mi][ni][1] + bb1;
                if (doRelu) { v0 = fmaxf(v0, 0.f); v1 = fmaxf(v1, 0.f); }
                C[(size_t)r0 * Nn + c0] = v0;
                C[(size_t)r0 * Nn + c0 + 1] = v1;
            }
            if (r0 + 8 < M) {
                float v2 = acc[mi][ni][2] + bb0;
                float v3 = acc[mi][ni][3] + bb1;
                if (doRelu) { v2 = fmaxf(v2, 0.f); v3 = fmaxf(v3, 0.f); }
                C[(size_t)(r0 + 8) * Nn + c0] = v2;
                C[(size_t)(r0 + 8) * Nn + c0 + 1] = v3;
            }
        }
    }
#undef LOAD_TILES
}

// ---------------- attention ----------------
__global__ void att_nd(const float* __restrict__ atts, const float* __restrict__ attd) {
    int n = blockIdx.x;
    int h = threadIdx.x >> 5;
    int l = threadIdx.x & 31;
    const float* row = g_hH + (size_t)n * (HH * DD) + h * DD;
    float s = 0.0f, d2 = 0.0f;
#pragma unroll
    for (int i = l; i < DD; i += 32) {
        float v = row[i];
        s += v * atts[h * DD + i];
        d2 += v * attd[h * DD + i];
    }
#pragma unroll
    for (int o = 16; o; o >>= 1) {
        s += __shfl_xor_sync(0xffffffffu, s, o);
        d2 += __shfl_xor_sync(0xffffffffu, d2, o);
    }
    if (l == 0) {
        g_asd[n * 8 + h] = s;
        g_asd[n * 8 + 4 + h] = d2;
    }
}

// thread per edge: alpha = leaky_relu(a_s[src] + a_d[dst] + tab[L][et])
__global__ void alpha_edges(const int* __restrict__ src, const int* __restrict__ dst,
                            const int* __restrict__ et, int L) {
    int e = blockIdx.x * blockDim.x + threadIdx.x;
    if (e >= EE) return;
    int s = src[e], d = dst[e], t = et[e];
    float4 as = *(const float4*)(g_asd + s * 8);
    float4 ad = *(const float4*)(g_asd + d * 8 + 4);
    float4 tb = *(const float4*)(&g_tab[L][t][0]);
    float4 r;
    r.x = as.x + ad.x + tb.x; r.x = r.x > 0.f ? r.x : 0.2f * r.x;
    r.y = as.y + ad.y + tb.y; r.y = r.y > 0.f ? r.y : 0.2f * r.y;
    r.z = as.z + ad.z + tb.z; r.z = r.z > 0.f ? r.z : 0.2f * r.z;
    r.w = as.w + ad.w + tb.w; r.w = r.w > 0.f ? r.w : 0.2f * r.w;
    *(float4*)(g_alpha + (size_t)e * 4) = r;
}

__device__ __forceinline__ float4 f4max(float4 a, float4 b) {
    return make_float4(fmaxf(a.x, b.x), fmaxf(a.y, b.y), fmaxf(a.z, b.z), fmaxf(a.w, b.w));
}

// fused: self-loop alpha + per-node softmax + aggregate + head-mean + bias + relu
__global__ void gat_node(const int* __restrict__ src, const int* __restrict__ et,
                         const float* __restrict__ bias, float* __restrict__ out, int L) {
    int n = blockIdx.x;
    int tid = threadIdx.x;      // 128
    __shared__ float s_mx[4], s_inv[4], s_selfw[4];
    __shared__ float sbuf[512];
    int p0 = g_off[n], p1 = g_off[n + 1];
    int deg = p1 - p0;

    if (tid < 32) {
        int lane = tid;
        // pass A: per-lane max of edge alphas + tab sum for self-loop attr
        float4 mx = make_float4(-1e30f, -1e30f, -1e30f, -1e30f);
        float4 ts = make_float4(0.f, 0.f, 0.f, 0.f);
        for (int p = p0 + lane; p < p1; p += 32) {
            int eid = g_eid[p];
            float4 r = *(const float4*)(g_alpha + (size_t)eid * 4);
            mx = f4max(mx, r);
            float4 tb = *(const float4*)(&g_tab[L][et[eid]][0]);
            ts.x += tb.x; ts.y += tb.y; ts.z += tb.z; ts.w += tb.w;
        }
#pragma unroll
        for (int o = 16; o; o >>= 1) {
            mx.x = fmaxf(mx.x, __shfl_xor_sync(0xffffffffu, mx.x, o));
            mx.y = fmaxf(mx.y, __shfl_xor_sync(0xffffffffu, mx.y, o));
            mx.z = fmaxf(mx.z, __shfl_xor_sync(0xffffffffu, mx.z, o));
            mx.w = fmaxf(mx.w, __shfl_xor_sync(0xffffffffu, mx.w, o));
            ts.x += __shfl_xor_sync(0xffffffffu, ts.x, o);
            ts.y += __shfl_xor_sync(0xffffffffu, ts.y, o);
            ts.z += __shfl_xor_sync(0xffffffffu, ts.z, o);
            ts.w += __shfl_xor_sync(0xffffffffu, ts.w, o);
        }
        // self-loop raw alpha
        float inv_deg = 1.0f / fmaxf((float)deg, 1.0f);
        float4 as = *(const float4*)(g_asd + n * 8);
        float4 ad = *(const float4*)(g_asd + n * 8 + 4);
        float4 sr;
        sr.x = as.x + ad.x + ts.x * inv_deg; sr.x = sr.x > 0.f ? sr.x : 0.2f * sr.x;
        sr.y = as.y + ad.y + ts.y * inv_deg; sr.y = sr.y > 0.f ? sr.y : 0.2f * sr.y;
        sr.z = as.z + ad.z + ts.z * inv_deg; sr.z = sr.z > 0.f ? sr.z : 0.2f * sr.z;
        sr.w = as.w + ad.w + ts.w * inv_deg; sr.w = sr.w > 0.f ? sr.w : 0.2f * sr.w;
        mx = f4max(mx, sr);
        // pass B: exp-sum
        float4 sm = make_float4(0.f, 0.f, 0.f, 0.f);
        if (lane == 0) {
            sm.x = __expf(sr.x - mx.x);
            sm.y = __expf(sr.y - mx.y);
            sm.z = __expf(sr.z - mx.z);
            sm.w = __expf(sr.w - mx.w);
        }
        for (int p = p0 + lane; p < p1; p += 32) {
            int eid = g_eid[p];
            float4 r = *(const float4*)(g_alpha + (size_t)eid * 4);
            sm.x += __expf(r.x - mx.x);
            sm.y += __expf(r.y - mx.y);
            sm.z += __expf(r.z - mx.z);
            sm.w += __expf(r.w - mx.w);
        }
#pragma unroll
        for (int o = 16; o; o >>= 1) {
            sm.x += __shfl_xor_sync(0xffffffffu, sm.x, o);
            sm.y += __shfl_xor_sync(0xffffffffu, sm.y, o);
            sm.z += __shfl_xor_sync(0xffffffffu, sm.z, o);
            sm.w += __shfl_xor_sync(0xffffffffu, sm.w, o);
        }
        if (lane == 0) {
            s_mx[0] = mx.x; s_mx[1] = mx.y; s_mx[2] = mx.z; s_mx[3] = mx.w;
            float i0 = 1.0f / (sm.x + 1e-16f), i1 = 1.0f / (sm.y + 1e-16f);
            float i2 = 1.0f / (sm.z + 1e-16f), i3 = 1.0f / (sm.w + 1e-16f);
            s_inv[0] = i0; s_inv[1] = i1; s_inv[2] = i2; s_inv[3] = i3;
            s_selfw[0] = __expf(sr.x - mx.x) * i0;
            s_selfw[1] = __expf(sr.y - mx.y) * i1;
            s_selfw[2] = __expf(sr.z - mx.z) * i2;
            s_selfw[3] = __expf(sr.w - mx.w) * i3;
        }
    }
    __syncthreads();
    int head = tid >> 5;
    float mxh = s_mx[head], invh = s_inv[head];
    const float4* hH4 = (const float4*)g_hH;
    float4 acc = make_float4(0.f, 0.f, 0.f, 0.f);
    for (int p = p0; p < p1; p++) {
        int eid = g_eid[p];
        int s = src[eid];
        float w = __expf(g_alpha[(size_t)eid * 4 + head] - mxh) * invh;
        float4 v = hH4[(size_t)s * 128 + tid];
        acc.x += w * v.x; acc.y += w * v.y; acc.z += w * v.z; acc.w += w * v.w;
    }
    {
        float w = s_selfw[head];
        float4 v = hH4[(size_t)n * 128 + tid];
        acc.x += w * v.x; acc.y += w * v.y; acc.z += w * v.z; acc.w += w * v.w;
    }
    *(float4*)&sbuf[tid * 4] = acc;
    __syncthreads();
    if (tid < 32) {
#pragma unroll
        for (int j = 0; j < 4; j++) {
            int d = tid * 4 + j;
            float v = 0.25f * (sbuf[d] + sbuf[128 + d] + sbuf[256 + d] + sbuf[384 + d]) + bias[d];
            out[(size_t)n * 128 + d] = fmaxf(v, 0.0f);
        }
    }
}

// ---------------- host ----------------
static float* symaddr(const void* s) {
    void* p = nullptr;
    cudaGetSymbolAddress(&p, s);
    return (float*)p;
}

extern "C" void kernel_launch(void* const* d_in, const int* in_sizes, int n_in,
                              void* d_out, int out_size) {
    const float* x   = (const float*)d_in[0];
    const int*   ei  = (const int*)d_in[1];
    const int*   et  = (const int*)d_in[2];
    const float* w1  = (const float*)d_in[3];
    const float* b1  = (const float*)d_in[4];
    const float* w2  = (const float*)d_in[5];
    const float* b2  = (const float*)d_in[6];
    const float* rel = (const float*)d_in[7];
    const float* lin[2]  = {(const float*)d_in[8],  (const float*)d_in[14]};
    const float* line[2] = {(const float*)d_in[9],  (const float*)d_in[15]};
    const float* atts[2] = {(const float*)d_in[10], (const float*)d_in[16]};
    const float* attd[2] = {(const float*)d_in[11], (const float*)d_in[17]};
    const float* atte[2] = {(const float*)d_in[12], (const float*)d_in[18]};
    const float* bias[2] = {(const float*)d_in[13], (const float*)d_in[19]};
    const int* srcp = ei;
    const int* dstp = ei + EE;

    float* pxp = symaddr(g_xp);
    float* ph1 = symaddr(g_h1);
    float* px  = symaddr(g_x);
    float* phH = symaddr(g_hH);

    zero_deg<<<(NN + 256) / 256, 256>>>();
    count_deg<<<(EE + 255) / 256, 256>>>(dstp);
    scan_k1<<<SCANB, 128>>>();
    scan_k2<<<1, 256>>>();
    scan_k3<<<SCANB, 128>>>();
    scatter_csr<<<(EE + 255) / 256, 256>>>(dstp);
    pad_x<<<(int)(((size_t)NN * KPAD + 255) / 256), 256>>>(x);
    compute_tab<<<1, 256>>>(rel, line[0], atte[0], line[1], atte[1]);

    // node encoder
    mma_gemm<<<dim3(HID / 128, (NN + 127) / 128), 256>>>(pxp, w1, b1, ph1, NN, KPAD, FIN, HID, 1);
    mma_gemm<<<dim3(DD / 128, (NN + 127) / 128), 256>>>(ph1, w2, b2, px, NN, HID, HID, DD, 0);

    for (int L = 0; L < 2; L++) {
        mma_gemm<<<dim3((HH * DD) / 128, (NN + 127) / 128), 256>>>(
            px, lin[L], nullptr, phH, NN, DD, DD, HH * DD, 0);
        att_nd<<<NN, 128>>>(atts[L], attd[L]);
        alpha_edges<<<(EE + 255) / 256, 256>>>(srcp, dstp, et, L);
        gat_node<<<NN, 128>>>(srcp, et, bias[L], (L == 0) ? px : (float*)d_out, L);
    }
}

// round 5
// speedup vs baseline: 1.3326x; 1.3326x over previous
#include <cuda_runtime.h>
#include <math.h>
#include <stdint.h>

#define NN   20000
#define EE   320000
#define FIN  518
#define KPAD 528
#define DD   128
#define EDIM 32
#define HH   4
#define RR   26
#define HID  256
#define SCANB ((NN + 127) / 128)
#define PADB  ((int)(((size_t)NN * KPAD + 255) / 256))
#define ZERB  ((NN + 256) / 256)

// ---------------- scratch ----------------
__device__ float g_xp[(size_t)NN * KPAD];
__device__ float g_h1[(size_t)NN * HID];
__device__ float g_x[(size_t)NN * DD];
__device__ float g_hH[(size_t)NN * HH * DD];
__device__ __align__(16) float g_asd[NN * 2 * HH];   // [n][0..3]=a_s, [n][4..7]=a_d
__device__ __align__(16) float g_alpha[(size_t)EE * HH];
__device__ __align__(16) float g_tab[2][RR][HH];
__device__ float g_ws[2][8][DD];                     // folded lin@att (h<4: att_s, h>=4: att_d)
__device__ int   g_deg[NN + 1];
__device__ int   g_off[NN + 1];
__device__ int   g_cur[NN];
__device__ int   g_eid[EE];
__device__ unsigned long long g_scanstate[SCANB];

// ---------------- setup: pad_x + zero_deg + tab + ws folds + scanstate zero ----------------
__global__ void setup(const float* __restrict__ x, const float* __restrict__ rel,
                      const float* __restrict__ line0, const float* __restrict__ atte0,
                      const float* __restrict__ line1, const float* __restrict__ atte1,
                      const float* __restrict__ lin0, const float* __restrict__ atts0,
                      const float* __restrict__ attd0,
                      const float* __restrict__ lin1, const float* __restrict__ atts1,
                      const float* __restrict__ attd1) {
    int b = blockIdx.x, tid = threadIdx.x;
    if (b < PADB) {
        size_t i = (size_t)b * 256 + tid;
        if (i < (size_t)NN * KPAD) {
            int n = (int)(i / KPAD), c = (int)(i % KPAD);
            g_xp[i] = (c < FIN) ? x[(size_t)n * FIN + c] : 0.0f;
        }
        return;
    }
    b -= PADB;
    if (b < ZERB) {
        int i = b * 256 + tid;
        if (i <= NN) g_deg[i] = 0;
        return;
    }
    b -= ZERB;
    if (b == 0) {
        // relation-type attention table
        __shared__ float we[2][HH][EDIM];
        if (tid < 2 * HH * EDIM) {
            int L = tid >> 7, rem = tid & 127;
            int h = rem / EDIM, c = rem % EDIM;
            const float* line = L ? line1 : line0;
            const float* atte = L ? atte1 : atte0;
            float s = 0.0f;
            for (int d = 0; d < DD; d++)
                s += line[(size_t)c * (HH * DD) + h * DD + d] * atte[h * DD + d];
            we[L][h][c] = s;
        }
        __syncthreads();
        if (tid < 2 * RR * HH) {
            int L = tid / (RR * HH), rem = tid % (RR * HH);
            int r = rem / HH, h = rem % HH;
            float s = 0.0f;
            for (int c = 0; c < EDIM; c++)
                s += rel[r * EDIM + c] * we[L][h][c];
            g_tab[L][r][h] = s;
        }
        if (tid < SCANB) g_scanstate[tid] = 0ULL;
        return;
    }
    // fold blocks: 2048 outputs over 8 blocks of 256 threads
    b -= 1;
    int idx = b * 256 + tid;                 // 0..2047 = [L][h8][k]
    if (idx < 2 * 8 * DD) {
        int L = idx / (8 * DD), rem = idx % (8 * DD);
        int h8 = rem / DD, k = rem % DD;
        const float* lin = L ? lin1 : lin0;
        const float* att;
        int h = h8 & 3;
        if (h8 < 4) att = L ? atts1 : atts0;
        else        att = L ? attd1 : attd0;
        float s = 0.0f;
        for (int d = 0; d < DD; d++)
            s += lin[(size_t)k * (HH * DD) + h * DD + d] * att[h * DD + d];
        g_ws[L][h8][k] = s;
    }
}

__global__ void count_deg(const int* __restrict__ dst) {
    int e = blockIdx.x * blockDim.x + threadIdx.x;
    if (e < EE) atomicAdd(&g_deg[dst[e]], 1);
}

// single-pass decoupled-lookback exclusive scan of g_deg -> g_off/g_cur
__global__ void scan_lookback() {
    int b = blockIdx.x, tid = threadIdx.x;     // 128 threads
    int lane = tid & 31, warp = tid >> 5;
    int i = b * 128 + tid;
    int v = (i < NN) ? g_deg[i] : 0;
    int incl = v;
#pragma unroll
    for (int o = 1; o < 32; o <<= 1) {
        int t = __shfl_up_sync(0xffffffffu, incl, o);
        if (lane >= o) incl += t;
    }
    __shared__ int wsum[4];
    __shared__ int s_prev;
    if (lane == 31) wsum[warp] = incl;
    __syncthreads();
    int wbase = 0;
    for (int w = 0; w < warp; w++) wbase += wsum[w];
    int incl_b = wbase + incl;
    int total = wsum[0] + wsum[1] + wsum[2] + wsum[3];

    if (tid == 0) {
        if (b == 0) {
            atomicExch(&g_scanstate[0], (2ULL << 32) | (unsigned)total);
            s_prev = 0;
        } else {
            atomicExch(&g_scanstate[b], (1ULL << 32) | (unsigned)total);
            long long run = 0;
            int j = b - 1;
            while (1) {
                unsigned long long st;
                do { st = atomicOr(&g_scanstate[j], 0ULL); } while ((st >> 32) == 0ULL);
                run += (long long)(st & 0xffffffffULL);
                if ((st >> 32) == 2ULL) break;
                j--;
            }
            s_prev = (int)run;
            atomicExch(&g_scanstate[b], (2ULL << 32) | (unsigned)(run + total));
        }
    }
    __syncthreads();
    int excl = s_prev + incl_b - v;
    if (i < NN) {
        g_off[i] = excl;
        g_cur[i] = excl;
        if (i == NN - 1) g_off[NN] = excl + v;
    }
}

__global__ void scatter_csr(const int* __restrict__ dst) {
    int e = blockIdx.x * blockDim.x + threadIdx.x;
    if (e >= EE) return;
    int pos = atomicAdd(&g_cur[dst[e]], 1);
    g_eid[pos] = e;
}

// ---------------- tf32 tensor-core GEMM (1xTF32) ----------------
__device__ __forceinline__ float to_tf32(float v) {
    uint32_t h;
    asm("cvt.rna.tf32.f32 %0, %1;" : "=r"(h) : "f"(v));
    return __uint_as_float(h);
}

__device__ __forceinline__ void mma8(float* c, const uint32_t* a, uint32_t b0, uint32_t b1) {
    asm volatile(
        "mma.sync.aligned.m16n8k8.row.col.f32.tf32.tf32.f32 "
        "{%0,%1,%2,%3}, {%4,%5,%6,%7}, {%8,%9}, {%0,%1,%2,%3};\n"
        : "+f"(c[0]), "+f"(c[1]), "+f"(c[2]), "+f"(c[3])
        : "r"(a[0]), "r"(a[1]), "r"(a[2]), "r"(a[3]), "r"(b0), "r"(b1));
}

__global__ __launch_bounds__(256, 2)
void mma_gemm(const float* __restrict__ A, const float* __restrict__ B,
              const float* __restrict__ bias, float* __restrict__ C,
              int M, int K, int KB, int Nn, int doRelu) {
    __shared__ float As[2][16][136];
    __shared__ float Bs[2][16][136];
    const int tid = threadIdx.x;
    const int warp = tid >> 5, lane = tid & 31;
    const int g = lane >> 2, tg = lane & 3;
    const int warpM = warp >> 1, warpN = warp & 1;
    const int rowBase = blockIdx.y * 128, colBase = blockIdx.x * 128;

    const int arow = tid >> 1, acol = (tid & 1) * 8;
    const int brow = tid >> 4, bcol = (tid & 15) * 8;

    float acc[2][8][4];
#pragma unroll
    for (int mi = 0; mi < 2; mi++)
#pragma unroll
        for (int ni = 0; ni < 8; ni++)
#pragma unroll
            for (int r = 0; r < 4; r++) acc[mi][ni][r] = 0.0f;

    const int nk = K / 16;

#define LOAD_TILES(BUF, K0)                                                       \
    {                                                                             \
        int grow = rowBase + arow;                                                \
        _Pragma("unroll")                                                         \
        for (int h = 0; h < 2; h++) {                                             \
            float4 v = make_float4(0.f, 0.f, 0.f, 0.f);                           \
            if (grow < M) v = *(const float4*)(A + (size_t)grow * K + (K0) + acol + h * 4); \
            As[BUF][acol + h * 4 + 0][arow] = to_tf32(v.x);                       \
            As[BUF][acol + h * 4 + 1][arow] = to_tf32(v.y);                       \
            As[BUF][acol + h * 4 + 2][arow] = to_tf32(v.z);                       \
            As[BUF][acol + h * 4 + 3][arow] = to_tf32(v.w);                       \
        }                                                                         \
        int kr = (K0) + brow;                                                     \
        _Pragma("unroll")                                                         \
        for (int h = 0; h < 2; h++) {                                             \
            float4 v = make_float4(0.f, 0.f, 0.f, 0.f);                           \
            if (kr < KB) v = *(const float4*)(B + (size_t)kr * Nn + colBase + bcol + h * 4); \
            v.x = to_tf32(v.x); v.y = to_tf32(v.y);                               \
            v.z = to_tf32(v.z); v.w = to_tf32(v.w);                               \
            *(float4*)&Bs[BUF][brow][bcol + h * 4] = v;                           \
        }                                                                         \
    }

    LOAD_TILES(0, 0)
    __syncthreads();

    for (int t = 0; t < nk; t++) {
        int buf = t & 1;
        if (t + 1 < nk) LOAD_TILES(buf ^ 1, (t + 1) * 16)

#pragma unroll
        for (int ks = 0; ks < 16; ks += 8) {
            uint32_t a[2][4];
#pragma unroll
            for (int mi = 0; mi < 2; mi++) {
                int mb = warpM * 32 + mi * 16 + g;
                a[mi][0] = __float_as_uint(As[buf][ks + tg][mb]);
                a[mi][1] = __float_as_uint(As[buf][ks + tg][mb + 8]);
                a[mi][2] = __float_as_uint(As[buf][ks + tg + 4][mb]);
                a[mi][3] = __float_as_uint(As[buf][ks + tg + 4][mb + 8]);
            }
#pragma unroll
            for (int ni = 0; ni < 8; ni++) {
                int nb = warpN * 64 + ni * 8 + g;
                uint32_t b0 = __float_as_uint(Bs[buf][ks + tg][nb]);
                uint32_t b1 = __float_as_uint(Bs[buf][ks + tg + 4][nb]);
#pragma unroll
                for (int mi = 0; mi < 2; mi++)
                    mma8(acc[mi][ni], a[mi], b0, b1);
            }
        }
        __syncthreads();
    }

#pragma unroll
    for (int mi = 0; mi < 2; mi++) {
        int r0 = rowBase + warpM * 32 + mi * 16 + g;
#pragma unroll
        for (int ni = 0; ni < 8; ni++) {
            int c0 = colBase + warpN * 64 + ni * 8 + tg * 2;
            float bb0 = bias ? bias[c0] : 0.0f;
            float bb1 = bias ? bias[c0 + 1] : 0.0f;
            if (r0 < M) {
                float v0 = acc[mi][ni][0] + bb0;
                float v1 = acc[mi][ni][1] + bb1;
                if (doRelu) { v0 = fmaxf(v0, 0.f); v1 = fmaxf(v1, 0.f); }
                C[(size_t)r0 * Nn + c0] = v0;
                C[(size_t)r0 * Nn + c0 + 1] = v1;
            }
            if (r0 + 8 < M) {
                float v2 = acc[mi][ni][2] + bb0;
                float v3 = acc[mi][ni][3] + bb1;
                if (doRelu) { v2 = fmaxf(v2, 0.f); v3 = fmaxf(v3, 0.f); }
                C[(size_t)(r0 + 8) * Nn + c0] = v2;
                C[(size_t)(r0 + 8) * Nn + c0 + 1] = v3;
            }
        }
    }
#undef LOAD_TILES
}

// ---------------- a_s/a_d for layer 0 from g_x (warp per node) ----------------
__global__ void asd0() {
    int n = blockIdx.x * 8 + (threadIdx.x >> 5);
    int lane = threadIdx.x & 31;
    if (n >= NN) return;
    float4 xv = *(const float4*)(g_x + (size_t)n * DD + lane * 4);
    float r[8];
#pragma unroll
    for (int h = 0; h < 8; h++) {
        const float* w = &g_ws[0][h][lane * 4];
        float p = xv.x * w[0] + xv.y * w[1] + xv.z * w[2] + xv.w * w[3];
#pragma unroll
        for (int o = 16; o; o >>= 1) p += __shfl_xor_sync(0xffffffffu, p, o);
        r[h] = p;
    }
    if (lane < 8) g_asd[n * 8 + lane] = r[lane];
}

// ---------------- per-edge raw alpha ----------------
__global__ void alpha_edges(const int* __restrict__ src, const int* __restrict__ dst,
                            const int* __restrict__ et, int L) {
    int e = blockIdx.x * blockDim.x + threadIdx.x;
    if (e >= EE) return;
    int s = src[e], d = dst[e], t = et[e];
    float4 as = *(const float4*)(g_asd + s * 8);
    float4 ad = *(const float4*)(g_asd + d * 8 + 4);
    float4 tb = *(const float4*)(&g_tab[L][t][0]);
    float4 r;
    r.x = as.x + ad.x + tb.x; r.x = r.x > 0.f ? r.x : 0.2f * r.x;
    r.y = as.y + ad.y + tb.y; r.y = r.y > 0.f ? r.y : 0.2f * r.y;
    r.z = as.z + ad.z + tb.z; r.z = r.z > 0.f ? r.z : 0.2f * r.z;
    r.w = as.w + ad.w + tb.w; r.w = r.w > 0.f ? r.w : 0.2f * r.w;
    *(float4*)(g_alpha + (size_t)e * 4) = r;
}

__device__ __forceinline__ float4 f4max(float4 a, float4 b) {
    return make_float4(fmaxf(a.x, b.x), fmaxf(a.y, b.y), fmaxf(a.z, b.z), fmaxf(a.w, b.w));
}

// fused: self-loop alpha + softmax + aggregate + head-mean + bias + relu (+next-layer asd)
__global__ void gat_node(const int* __restrict__ src, const int* __restrict__ et,
                         const float* __restrict__ bias, float* __restrict__ out, int L) {
    int n = blockIdx.x;
    int tid = threadIdx.x;      // 128
    __shared__ float s_mx[4], s_inv[4], s_selfw[4];
    __shared__ float sbuf[512];
    int p0 = g_off[n], p1 = g_off[n + 1];
    int deg = p1 - p0;

    if (tid < 32) {
        int lane = tid;
        float4 mx = make_float4(-1e30f, -1e30f, -1e30f, -1e30f);
        float4 ts = make_float4(0.f, 0.f, 0.f, 0.f);
        for (int p = p0 + lane; p < p1; p += 32) {
            int eid = g_eid[p];
            float4 r = *(const float4*)(g_alpha + (size_t)eid * 4);
            mx = f4max(mx, r);
            float4 tb = *(const float4*)(&g_tab[L][et[eid]][0]);
            ts.x += tb.x; ts.y += tb.y; ts.z += tb.z; ts.w += tb.w;
        }
#pragma unroll
        for (int o = 16; o; o >>= 1) {
            mx.x = fmaxf(mx.x, __shfl_xor_sync(0xffffffffu, mx.x, o));
            mx.y = fmaxf(mx.y, __shfl_xor_sync(0xffffffffu, mx.y, o));
            mx.z = fmaxf(mx.z, __shfl_xor_sync(0xffffffffu, mx.z, o));
            mx.w = fmaxf(mx.w, __shfl_xor_sync(0xffffffffu, mx.w, o));
            ts.x += __shfl_xor_sync(0xffffffffu, ts.x, o);
            ts.y += __shfl_xor_sync(0xffffffffu, ts.y, o);
            ts.z += __shfl_xor_sync(0xffffffffu, ts.z, o);
            ts.w += __shfl_xor_sync(0xffffffffu, ts.w, o);
        }
        float inv_deg = 1.0f / fmaxf((float)deg, 1.0f);
        float4 as = *(const float4*)(g_asd + n * 8);
        float4 ad = *(const float4*)(g_asd + n * 8 + 4);
        float4 sr;
        sr.x = as.x + ad.x + ts.x * inv_deg; sr.x = sr.x > 0.f ? sr.x : 0.2f * sr.x;
        sr.y = as.y + ad.y + ts.y * inv_deg; sr.y = sr.y > 0.f ? sr.y : 0.2f * sr.y;
        sr.z = as.z + ad.z + ts.z * inv_deg; sr.z = sr.z > 0.f ? sr.z : 0.2f * sr.z;
        sr.w = as.w + ad.w + ts.w * inv_deg; sr.w = sr.w > 0.f ? sr.w : 0.2f * sr.w;
        mx = f4max(mx, sr);
        float4 sm = make_float4(0.f, 0.f, 0.f, 0.f);
        if (lane == 0) {
            sm.x = __expf(sr.x - mx.x);
            sm.y = __expf(sr.y - mx.y);
            sm.z = __expf(sr.z - mx.z);
            sm.w = __expf(sr.w - mx.w);
        }
        for (int p = p0 + lane; p < p1; p += 32) {
            int eid = g_eid[p];
            float4 r = *(const float4*)(g_alpha + (size_t)eid * 4);
            sm.x += __expf(r.x - mx.x);
            sm.y += __expf(r.y - mx.y);
            sm.z += __expf(r.z - mx.z);
            sm.w += __expf(r.w - mx.w);
        }
#pragma unroll
        for (int o = 16; o; o >>= 1) {
            sm.x += __shfl_xor_sync(0xffffffffu, sm.x, o);
            sm.y += __shfl_xor_sync(0xffffffffu, sm.y, o);
            sm.z += __shfl_xor_sync(0xffffffffu, sm.z, o);
            sm.w += __shfl_xor_sync(0xffffffffu, sm.w, o);
        }
        if (lane == 0) {
            s_mx[0] = mx.x; s_mx[1] = mx.y; s_mx[2] = mx.z; s_mx[3] = mx.w;
            float i0 = 1.0f / (sm.x + 1e-16f), i1 = 1.0f / (sm.y + 1e-16f);
            float i2 = 1.0f / (sm.z + 1e-16f), i3 = 1.0f / (sm.w + 1e-16f);
            s_inv[0] = i0; s_inv[1] = i1; s_inv[2] = i2; s_inv[3] = i3;
            s_selfw[0] = __expf(sr.x - mx.x) * i0;
            s_selfw[1] = __expf(sr.y - mx.y) * i1;
            s_selfw[2] = __expf(sr.z - mx.z) * i2;
            s_selfw[3] = __expf(sr.w - mx.w) * i3;
        }
    }
    __syncthreads();
    int head = tid >> 5;
    float mxh = s_mx[head], invh = s_inv[head];
    const float4* hH4 = (const float4*)g_hH;
    float4 acc = make_float4(0.f, 0.f, 0.f, 0.f);
    int p = p0;
    for (; p + 2 <= p1; p += 2) {
        int eid0 = g_eid[p], eid1 = g_eid[p + 1];
        int s0 = src[eid0], s1 = src[eid1];
        float a0 = g_alpha[(size_t)eid0 * 4 + head];
        float a1 = g_alpha[(size_t)eid1 * 4 + head];
        float4 v0 = hH4[(size_t)s0 * 128 + tid];
        float4 v1 = hH4[(size_t)s1 * 128 + tid];
        float w0 = __expf(a0 - mxh) * invh;
        float w1 = __expf(a1 - mxh) * invh;
        acc.x += w0 * v0.x + w1 * v1.x;
        acc.y += w0 * v0.y + w1 * v1.y;
        acc.z += w0 * v0.z + w1 * v1.z;
        acc.w += w0 * v0.w + w1 * v1.w;
    }
    if (p < p1) {
        int eid = g_eid[p];
        int s = src[eid];
        float w = __expf(g_alpha[(size_t)eid * 4 + head] - mxh) * invh;
        float4 v = hH4[(size_t)s * 128 + tid];
        acc.x += w * v.x; acc.y += w * v.y; acc.z += w * v.z; acc.w += w * v.w;
    }
    {
        float w = s_selfw[head];
        float4 v = hH4[(size_t)n * 128 + tid];
        acc.x += w * v.x; acc.y += w * v.y; acc.z += w * v.z; acc.w += w * v.w;
    }
    *(float4*)&sbuf[tid * 4] = acc;
    __syncthreads();
    if (tid < 32) {
        float ov[4];
#pragma unroll
        for (int j = 0; j < 4; j++) {
            int d = tid * 4 + j;
            float v = 0.25f * (sbuf[d] + sbuf[128 + d] + sbuf[256 + d] + sbuf[384 + d]) + bias[d];
            v = fmaxf(v, 0.0f);
            ov[j] = v;
            out[(size_t)n * 128 + d] = v;
        }
        if (L == 0) {
            // epilogue: a_s/a_d for next layer from the just-computed row
            float r[8];
#pragma unroll
            for (int h = 0; h < 8; h++) {
                const float* w = &g_ws[1][h][tid * 4];
                float pp = ov[0] * w[0] + ov[1] * w[1] + ov[2] * w[2] + ov[3] * w[3];
#pragma unroll
                for (int o = 16; o; o >>= 1) pp += __shfl_xor_sync(0xffffffffu, pp, o);
                r[h] = pp;
            }
            if (tid < 8) g_asd[n * 8 + tid] = r[tid];
        }
    }
}

// ---------------- host ----------------
static float* symaddr(const void* s) {
    void* p = nullptr;
    cudaGetSymbolAddress(&p, s);
    return (float*)p;
}

extern "C" void kernel_launch(void* const* d_in, const int* in_sizes, int n_in,
                              void* d_out, int out_size) {
    const float* x   = (const float*)d_in[0];
    const int*   ei  = (const int*)d_in[1];
    const int*   et  = (const int*)d_in[2];
    const float* w1  = (const float*)d_in[3];
    const float* b1  = (const float*)d_in[4];
    const float* w2  = (const float*)d_in[5];
    const float* b2  = (const float*)d_in[6];
    const float* rel = (const float*)d_in[7];
    const float* lin[2]  = {(const float*)d_in[8],  (const float*)d_in[14]};
    const float* line[2] = {(const float*)d_in[9],  (const float*)d_in[15]};
    const float* atts[2] = {(const float*)d_in[10], (const float*)d_in[16]};
    const float* attd[2] = {(const float*)d_in[11], (const float*)d_in[17]};
    const float* atte[2] = {(const float*)d_in[12], (const float*)d_in[18]};
    const float* bias[2] = {(const float*)d_in[13], (const float*)d_in[19]};
    const int* srcp = ei;
    const int* dstp = ei + EE;

    float* pxp = symaddr(g_xp);
    float* ph1 = symaddr(g_h1);
    float* px  = symaddr(g_x);
    float* phH = symaddr(g_hH);

    // 0: setup (pad_x + zero_deg + tab + folds + scanstate)
    setup<<<PADB + ZERB + 1 + 8, 256>>>(x, rel, line[0], atte[0], line[1], atte[1],
                                        lin[0], atts[0], attd[0], lin[1], atts[1], attd[1]);
    // 1: degree histogram
    count_deg<<<(EE + 255) / 256, 256>>>(dstp);
    // 2: single-pass scan
    scan_lookback<<<SCANB, 128>>>();
    // 3: big GEMM (profiled launch)
    mma_gemm<<<dim3(HID / 128, (NN + 127) / 128), 256>>>(pxp, w1, b1, ph1, NN, KPAD, FIN, HID, 1);
    // 4: CSR scatter
    scatter_csr<<<(EE + 255) / 256, 256>>>(dstp);
    // 5: encoder GEMM 2
    mma_gemm<<<dim3(DD / 128, (NN + 127) / 128), 256>>>(ph1, w2, b2, px, NN, HID, HID, DD, 0);
    // 6: layer-0 a_s/a_d
    asd0<<<(NN + 7) / 8, 256>>>();

    for (int L = 0; L < 2; L++) {
        mma_gemm<<<dim3((HH * DD) / 128, (NN + 127) / 128), 256>>>(
            px, lin[L], nullptr, phH, NN, DD, DD, HH * DD, 0);
        alpha_edges<<<(EE + 255) / 256, 256>>>(srcp, dstp, et, L);
        gat_node<<<NN, 128>>>(srcp, et, bias[L], (L == 0) ? px : (float*)d_out, L);
    }
}

// round 7
// speedup vs baseline: 1.5635x; 1.1733x over previous
#include <cuda_runtime.h>
#include <cuda_fp16.h>
#include <math.h>
#include <stdint.h>

#define NN   20000
#define EE   320000
#define FIN  518
#define KPAD 528
#define DD   128
#define EDIM 32
#define HH   4
#define RR   26
#define HID  256
#define SCANB ((NN + 127) / 128)
#define PADB  ((int)(((size_t)NN * KPAD + 255) / 256))
#define ZERB  ((NN + 256) / 256)

// ---------------- scratch ----------------
__device__ float g_xp[(size_t)NN * KPAD];
__device__ float g_h1[(size_t)NN * HID];
__device__ float g_x[(size_t)NN * DD];
__device__ __half g_hHh[(size_t)NN * HH * DD];          // per-head feats, fp16
__device__ __align__(16) float g_asd[2][NN * 8];        // [L][n*8 + (0..3 a_s | 4..7 a_d)]
__device__ __align__(16) float g_tab[2][RR][HH];
__device__ float g_ws[2][8][DD];
__device__ int   g_deg[NN + 1];
__device__ int   g_off[NN + 1];
__device__ int   g_cur[NN];
__device__ int   g_eid[EE];
__device__ unsigned long long g_scanstate[SCANB];

// ---------------- setup ----------------
__global__ void setup(const float* __restrict__ x, const float* __restrict__ rel,
                      const float* __restrict__ line0, const float* __restrict__ atte0,
                      const float* __restrict__ line1, const float* __restrict__ atte1,
                      const float* __restrict__ lin0, const float* __restrict__ atts0,
                      const float* __restrict__ attd0,
                      const float* __restrict__ lin1, const float* __restrict__ atts1,
                      const float* __restrict__ attd1) {
    int b = blockIdx.x, tid = threadIdx.x;
    if (b < PADB) {
        size_t i = (size_t)b * 256 + tid;
        if (i < (size_t)NN * KPAD) {
            int n = (int)(i / KPAD), c = (int)(i % KPAD);
            g_xp[i] = (c < FIN) ? x[(size_t)n * FIN + c] : 0.0f;
        }
        return;
    }
    b -= PADB;
    if (b < ZERB) {
        int i = b * 256 + tid;
        if (i <= NN) g_deg[i] = 0;
        return;
    }
    b -= ZERB;
    if (b == 0) {
        __shared__ float we[2][HH][EDIM];
        if (tid < 2 * HH * EDIM) {
            int L = tid >> 7, rem = tid & 127;
            int h = rem / EDIM, c = rem % EDIM;
            const float* line = L ? line1 : line0;
            const float* atte = L ? atte1 : atte0;
            float s = 0.0f;
            for (int d = 0; d < DD; d++)
                s += line[(size_t)c * (HH * DD) + h * DD + d] * atte[h * DD + d];
            we[L][h][c] = s;
        }
        __syncthreads();
        if (tid < 2 * RR * HH) {
            int L = tid / (RR * HH), rem = tid % (RR * HH);
            int r = rem / HH, h = rem % HH;
            float s = 0.0f;
            for (int c = 0; c < EDIM; c++)
                s += rel[r * EDIM + c] * we[L][h][c];
            g_tab[L][r][h] = s;
        }
        if (tid < SCANB) g_scanstate[tid] = 0ULL;
        return;
    }
    b -= 1;
    int idx = b * 256 + tid;                 // [L][h8][k]
    if (idx < 2 * 8 * DD) {
        int L = idx / (8 * DD), rem = idx % (8 * DD);
        int h8 = rem / DD, k = rem % DD;
        const float* lin = L ? lin1 : lin0;
        const float* att;
        int h = h8 & 3;
        if (h8 < 4) att = L ? atts1 : atts0;
        else        att = L ? attd1 : attd0;
        float s = 0.0f;
        for (int d = 0; d < DD; d++)
            s += lin[(size_t)k * (HH * DD) + h * DD + d] * att[h * DD + d];
        g_ws[L][h8][k] = s;
    }
}

__global__ void count_deg(const int* __restrict__ dst) {
    int e = blockIdx.x * blockDim.x + threadIdx.x;
    if (e < EE) atomicAdd(&g_deg[dst[e]], 1);
}

__global__ void scan_lookback() {
    int b = blockIdx.x, tid = threadIdx.x;     // 128 threads
    int lane = tid & 31, warp = tid >> 5;
    int i = b * 128 + tid;
    int v = (i < NN) ? g_deg[i] : 0;
    int incl = v;
#pragma unroll
    for (int o = 1; o < 32; o <<= 1) {
        int t = __shfl_up_sync(0xffffffffu, incl, o);
        if (lane >= o) incl += t;
    }
    __shared__ int wsum[4];
    __shared__ int s_prev;
    if (lane == 31) wsum[warp] = incl;
    __syncthreads();
    int wbase = 0;
    for (int w = 0; w < warp; w++) wbase += wsum[w];
    int incl_b = wbase + incl;
    int total = wsum[0] + wsum[1] + wsum[2] + wsum[3];

    if (tid == 0) {
        if (b == 0) {
            atomicExch(&g_scanstate[0], (2ULL << 32) | (unsigned)total);
            s_prev = 0;
        } else {
            atomicExch(&g_scanstate[b], (1ULL << 32) | (unsigned)total);
            long long run = 0;
            int j = b - 1;
            while (1) {
                unsigned long long st;
                do { st = atomicOr(&g_scanstate[j], 0ULL); } while ((st >> 32) == 0ULL);
                run += (long long)(st & 0xffffffffULL);
                if ((st >> 32) == 2ULL) break;
                j--;
            }
            s_prev = (int)run;
            atomicExch(&g_scanstate[b], (2ULL << 32) | (unsigned)(run + total));
        }
    }
    __syncthreads();
    int excl = s_prev + incl_b - v;
    if (i < NN) {
        g_off[i] = excl;
        g_cur[i] = excl;
        if (i == NN - 1) g_off[NN] = excl + v;
    }
}

__global__ void scatter_csr(const int* __restrict__ dst) {
    int e = blockIdx.x * blockDim.x + threadIdx.x;
    if (e >= EE) return;
    int pos = atomicAdd(&g_cur[dst[e]], 1);
    g_eid[pos] = e;
}

// ---------------- tf32 tensor-core GEMM (1xTF32) ----------------
__device__ __forceinline__ float to_tf32(float v) {
    uint32_t h;
    asm("cvt.rna.tf32.f32 %0, %1;" : "=r"(h) : "f"(v));
    return __uint_as_float(h);
}

__device__ __forceinline__ void mma8(float* c, const uint32_t* a, uint32_t b0, uint32_t b1) {
    asm volatile(
        "mma.sync.aligned.m16n8k8.row.col.f32.tf32.tf32.f32 "
        "{%0,%1,%2,%3}, {%4,%5,%6,%7}, {%8,%9}, {%0,%1,%2,%3};\n"
        : "+f"(c[0]), "+f"(c[1]), "+f"(c[2]), "+f"(c[3])
        : "r"(a[0]), "r"(a[1]), "r"(a[2]), "r"(a[3]), "r"(b0), "r"(b1));
}

__global__ __launch_bounds__(256, 2)
void mma_gemm(const float* __restrict__ A, const float* __restrict__ B,
              const float* __restrict__ bias, void* __restrict__ C,
              int M, int K, int KB, int Nn, int doRelu, int doHalf) {
    __shared__ float As[2][16][136];
    __shared__ float Bs[2][16][136];
    const int tid = threadIdx.x;
    const int warp = tid >> 5, lane = tid & 31;
    const int g = lane >> 2, tg = lane & 3;
    const int warpM = warp >> 1, warpN = warp & 1;
    const int rowBase = blockIdx.y * 128, colBase = blockIdx.x * 128;

    const int arow = tid >> 1, acol = (tid & 1) * 8;
    const int brow = tid >> 4, bcol = (tid & 15) * 8;

    float acc[2][8][4];
#pragma unroll
    for (int mi = 0; mi < 2; mi++)
#pragma unroll
        for (int ni = 0; ni < 8; ni++)
#pragma unroll
            for (int r = 0; r < 4; r++) acc[mi][ni][r] = 0.0f;

    const int nk = K / 16;

#define LOAD_TILES(BUF, K0)                                                       \
    {                                                                             \
        int grow = rowBase + arow;                                                \
        _Pragma("unroll")                                                         \
        for (int h = 0; h < 2; h++) {                                             \
            float4 v = make_float4(0.f, 0.f, 0.f, 0.f);                           \
            if (grow < M) v = *(const float4*)(A + (size_t)grow * K + (K0) + acol + h * 4); \
            As[BUF][acol + h * 4 + 0][arow] = to_tf32(v.x);                       \
            As[BUF][acol + h * 4 + 1][arow] = to_tf32(v.y);                       \
            As[BUF][acol + h * 4 + 2][arow] = to_tf32(v.z);                       \
            As[BUF][acol + h * 4 + 3][arow] = to_tf32(v.w);                       \
        }                                                                         \
        int kr = (K0) + brow;                                                     \
        _Pragma("unroll")                                                         \
        for (int h = 0; h < 2; h++) {                                             \
            float4 v = make_float4(0.f, 0.f, 0.f, 0.f);                           \
            if (kr < KB) v = *(const float4*)(B + (size_t)kr * Nn + colBase + bcol + h * 4); \
            v.x = to_tf32(v.x); v.y = to_tf32(v.y);                               \
            v.z = to_tf32(v.z); v.w = to_tf32(v.w);                               \
            *(float4*)&Bs[BUF][brow][bcol + h * 4] = v;                           \
        }                                                                         \
    }

    LOAD_TILES(0, 0)
    __syncthreads();

    for (int t = 0; t < nk; t++) {
        int buf = t & 1;
        if (t + 1 < nk) LOAD_TILES(buf ^ 1, (t + 1) * 16)

#pragma unroll
        for (int ks = 0; ks < 16; ks += 8) {
            uint32_t a[2][4];
#pragma unroll
            for (int mi = 0; mi < 2; mi++) {
                int mb = warpM * 32 + mi * 16 + g;
                a[mi][0] = __float_as_uint(As[buf][ks + tg][mb]);
                a[mi][1] = __float_as_uint(As[buf][ks + tg][mb + 8]);
                a[mi][2] = __float_as_uint(As[buf][ks + tg + 4][mb]);
                a[mi][3] = __float_as_uint(As[buf][ks + tg + 4][mb + 8]);
            }
#pragma unroll
            for (int ni = 0; ni < 8; ni++) {
                int nb = warpN * 64 + ni * 8 + g;
                uint32_t b0 = __float_as_uint(Bs[buf][ks + tg][nb]);
                uint32_t b1 = __float_as_uint(Bs[buf][ks + tg + 4][nb]);
#pragma unroll
                for (int mi = 0; mi < 2; mi++)
                    mma8(acc[mi][ni], a[mi], b0, b1);
            }
        }
        __syncthreads();
    }

#pragma unroll
    for (int mi = 0; mi < 2; mi++) {
        int r0 = rowBase + warpM * 32 + mi * 16 + g;
#pragma unroll
        for (int ni = 0; ni < 8; ni++) {
            int c0 = colBase + warpN * 64 + ni * 8 + tg * 2;
            float bb0 = bias ? bias[c0] : 0.0f;
            float bb1 = bias ? bias[c0 + 1] : 0.0f;
            float v0 = acc[mi][ni][0] + bb0;
            float v1 = acc[mi][ni][1] + bb1;
            float v2 = acc[mi][ni][2] + bb0;
            float v3 = acc[mi][ni][3] + bb1;
            if (doRelu) {
                v0 = fmaxf(v0, 0.f); v1 = fmaxf(v1, 0.f);
                v2 = fmaxf(v2, 0.f); v3 = fmaxf(v3, 0.f);
            }
            if (doHalf) {
                __half* Ch = (__half*)C;
                if (r0 < M)
                    *(__half2*)(Ch + (size_t)r0 * Nn + c0) = __floats2half2_rn(v0, v1);
                if (r0 + 8 < M)
                    *(__half2*)(Ch + (size_t)(r0 + 8) * Nn + c0) = __floats2half2_rn(v2, v3);
            } else {
                float* Cf = (float*)C;
                if (r0 < M) {
                    Cf[(size_t)r0 * Nn + c0] = v0;
                    Cf[(size_t)r0 * Nn + c0 + 1] = v1;
                }
                if (r0 + 8 < M) {
                    Cf[(size_t)(r0 + 8) * Nn + c0] = v2;
                    Cf[(size_t)(r0 + 8) * Nn + c0 + 1] = v3;
                }
            }
        }
    }
#undef LOAD_TILES
}

// ---------------- a_s/a_d for layer 0 from g_x (warp per node) ----------------
__global__ void asd0() {
    int n = blockIdx.x * 8 + (threadIdx.x >> 5);
    int lane = threadIdx.x & 31;
    if (n >= NN) return;
    float4 xv = *(const float4*)(g_x + (size_t)n * DD + lane * 4);
    float r[8];
#pragma unroll
    for (int h = 0; h < 8; h++) {
        const float* w = &g_ws[0][h][lane * 4];
        float p = xv.x * w[0] + xv.y * w[1] + xv.z * w[2] + xv.w * w[3];
#pragma unroll
        for (int o = 16; o; o >>= 1) p += __shfl_xor_sync(0xffffffffu, p, o);
        r[h] = p;
    }
    if (lane < 8) g_asd[0][n * 8 + lane] = r[lane];
}

// fused: on-the-fly alpha + single-pass softmax + aggregate + head-mean + bias + relu
__global__ void gat_node(const int* __restrict__ src, const int* __restrict__ et,
                         const float* __restrict__ bias, float* __restrict__ out, int L) {
    int n = blockIdx.x;
    int tid = threadIdx.x;      // 128
    __shared__ float tab_sm[RR * HH];
    __shared__ float sbuf[512];
    if (tid < RR * HH) tab_sm[tid] = ((const float*)g_tab)[L * RR * HH + tid];
    __syncthreads();

    const float* asd = g_asd[L];
    int p0 = g_off[n], p1 = g_off[n + 1];
    int deg = p1 - p0;
    int head = tid >> 5;
    float adn = asd[n * 8 + 4 + head];

    const uint2* hrow_base = (const uint2*)g_hHh;   // 8B = 4 halfs per thread
    float4 acc = make_float4(0.f, 0.f, 0.f, 0.f);
    float wsum = 0.0f, tsum = 0.0f;

    int p = p0;
    for (; p + 2 <= p1; p += 2) {
        int eid0 = g_eid[p], eid1 = g_eid[p + 1];
        int s0 = src[eid0], s1 = src[eid1];
        int t0 = et[eid0], t1 = et[eid1];
        float tb0 = tab_sm[t0 * HH + head];
        float tb1 = tab_sm[t1 * HH + head];
        float r0 = asd[s0 * 8 + head] + adn + tb0;
        float r1 = asd[s1 * 8 + head] + adn + tb1;
        uint2 u0 = hrow_base[(size_t)s0 * 128 + tid];
        uint2 u1 = hrow_base[(size_t)s1 * 128 + tid];
        r0 = r0 > 0.f ? r0 : 0.2f * r0;
        r1 = r1 > 0.f ? r1 : 0.2f * r1;
        float w0 = __expf(r0), w1 = __expf(r1);
        wsum += w0 + w1;
        tsum += tb0 + tb1;
        float2 f00 = __half22float2(*(__half2*)&u0.x);
        float2 f01 = __half22float2(*(__half2*)&u0.y);
        float2 f10 = __half22float2(*(__half2*)&u1.x);
        float2 f11 = __half22float2(*(__half2*)&u1.y);
        acc.x += w0 * f00.x + w1 * f10.x;
        acc.y += w0 * f00.y + w1 * f10.y;
        acc.z += w0 * f01.x + w1 * f11.x;
        acc.w += w0 * f01.y + w1 * f11.y;
    }
    if (p < p1) {
        int eid = g_eid[p];
        int s = src[eid], t = et[eid];
        float tb = tab_sm[t * HH + head];
        float r = asd[s * 8 + head] + adn + tb;
        r = r > 0.f ? r : 0.2f * r;
        float w = __expf(r);
        wsum += w; tsum += tb;
        uint2 u = hrow_base[(size_t)s * 128 + tid];
        float2 f0 = __half22float2(*(__half2*)&u.x);
        float2 f1 = __half22float2(*(__half2*)&u.y);
        acc.x += w * f0.x; acc.y += w * f0.y;
        acc.z += w * f1.x; acc.w += w * f1.y;
    }
    // self loop
    {
        float asn = asd[n * 8 + head];
        float sr = asn + adn + tsum / fmaxf((float)deg, 1.0f);
        sr = sr > 0.f ? sr : 0.2f * sr;
        float wself = __expf(sr);
        uint2 u = hrow_base[(size_t)n * 128 + tid];
        float2 f0 = __half22float2(*(__half2*)&u.x);
        float2 f1 = __half22float2(*(__half2*)&u.y);
        acc.x += wself * f0.x; acc.y += wself * f0.y;
        acc.z += wself * f1.x; acc.w += wself * f1.y;
        float inv = 1.0f / (wsum + wself + 1e-16f);
        acc.x *= inv; acc.y *= inv; acc.z *= inv; acc.w *= inv;
    }
    *(float4*)&sbuf[tid * 4] = acc;
    __syncthreads();
    if (tid < 32) {
        float ov[4];
#pragma unroll
        for (int j = 0; j < 4; j++) {
            int d = tid * 4 + j;
            float v = 0.25f * (sbuf[d] + sbuf[128 + d] + sbuf[256 + d] + sbuf[384 + d]) + bias[d];
            v = fmaxf(v, 0.0f);
            ov[j] = v;
            out[(size_t)n * 128 + d] = v;
        }
        if (L == 0) {
            // next-layer a_s/a_d into slot 1 (no race: slot 0 stays intact)
            float r[8];
#pragma unroll
            for (int h = 0; h < 8; h++) {
                const float* w = &g_ws[1][h][tid * 4];
                float pp = ov[0] * w[0] + ov[1] * w[1] + ov[2] * w[2] + ov[3] * w[3];
#pragma unroll
                for (int o = 16; o; o >>= 1) pp += __shfl_xor_sync(0xffffffffu, pp, o);
                r[h] = pp;
            }
            if (tid < 8) g_asd[1][n * 8 + tid] = r[tid];
        }
    }
}

// ---------------- host ----------------
static float* symaddr(const void* s) {
    void* p = nullptr;
    cudaGetSymbolAddress(&p, s);
    return (float*)p;
}

extern "C" void kernel_launch(void* const* d_in, const int* in_sizes, int n_in,
                              void* d_out, int out_size) {
    const float* x   = (const float*)d_in[0];
    const int*   ei  = (const int*)d_in[1];
    const int*   et  = (const int*)d_in[2];
    const float* w1  = (const float*)d_in[3];
    const float* b1  = (const float*)d_in[4];
    const float* w2  = (const float*)d_in[5];
    const float* b2  = (const float*)d_in[6];
    const float* rel = (const float*)d_in[7];
    const float* lin[2]  = {(const float*)d_in[8],  (const float*)d_in[14]};
    const float* line[2] = {(const float*)d_in[9],  (const float*)d_in[15]};
    const float* atts[2] = {(const float*)d_in[10], (const float*)d_in[16]};
    const float* attd[2] = {(const float*)d_in[11], (const float*)d_in[17]};
    const float* atte[2] = {(const float*)d_in[12], (const float*)d_in[18]};
    const float* bias[2] = {(const float*)d_in[13], (const float*)d_in[19]};
    const int* srcp = ei;
    const int* dstp = ei + EE;

    float* pxp = symaddr(g_xp);
    float* ph1 = symaddr(g_h1);
    float* px  = symaddr(g_x);
    void*  phH = (void*)symaddr(g_hHh);

    setup<<<PADB + ZERB + 1 + 8, 256>>>(x, rel, line[0], atte[0], line[1], atte[1],
                                        lin[0], atts[0], attd[0], lin[1], atts[1], attd[1]);
    count_deg<<<(EE + 255) / 256, 256>>>(dstp);
    scan_lookback<<<SCANB, 128>>>();
    mma_gemm<<<dim3(HID / 128, (NN + 127) / 128), 256>>>(pxp, w1, b1, ph1, NN, KPAD, FIN, HID, 1, 0);
    scatter_csr<<<(EE + 255) / 256, 256>>>(dstp);
    mma_gemm<<<dim3(DD / 128, (NN + 127) / 128), 256>>>(ph1, w2, b2, px, NN, HID, HID, DD, 0, 0);
    asd0<<<(NN + 7) / 8, 256>>>();

    for (int L = 0; L < 2; L++) {
        mma_gemm<<<dim3((HH * DD) / 128, (NN + 127) / 128), 256>>>(
            px, lin[L], nullptr, phH, NN, DD, DD, HH * DD, 0, 1);
        gat_node<<<NN, 128>>>(srcp, et, bias[L], (L == 0) ? px : (float*)d_out, L);
    }
}

// round 9
// speedup vs baseline: 1.7288x; 1.1057x over previous
#include <cuda_runtime.h>
#include <cuda_fp16.h>
#include <math.h>
#include <stdint.h>

#define NN   20000
#define EE   320000
#define FIN  518
#define KPAD 528
#define DD   128
#define EDIM 32
#define HH   4
#define RR   26
#define HID  256
#define SCANB ((NN + 127) / 128)
#define PADB  ((int)(((size_t)NN * KPAD + 255) / 256))
#define ZERB  ((NN + 256) / 256)

// ---------------- scratch ----------------
__device__ float g_xp[(size_t)NN * KPAD];
__device__ float g_h1[(size_t)NN * HID];
__device__ float g_x[(size_t)NN * DD];
__device__ __half g_hHh[(size_t)NN * HH * DD];          // per-head feats, fp16
__device__ __align__(16) float g_asd[2][NN * 8];        // [L][n*8 + (0..3 a_s | 4..7 a_d)]
__device__ __align__(16) float g_tab[2][RR][HH];
__device__ float g_ws[2][8][DD];
__device__ int   g_deg[NN + 1];
__device__ int   g_off[NN + 1];
__device__ int   g_cur[NN];
__device__ int   g_eid[EE];
__device__ unsigned long long g_scanstate[SCANB];

// ---------------- setup ----------------
__global__ void setup(const float* __restrict__ x, const float* __restrict__ rel,
                      const float* __restrict__ line0, const float* __restrict__ atte0,
                      const float* __restrict__ line1, const float* __restrict__ atte1,
                      const float* __restrict__ lin0, const float* __restrict__ atts0,
                      const float* __restrict__ attd0,
                      const float* __restrict__ lin1, const float* __restrict__ atts1,
                      const float* __restrict__ attd1) {
    int b = blockIdx.x, tid = threadIdx.x;
    if (b < PADB) {
        size_t i = (size_t)b * 256 + tid;
        if (i < (size_t)NN * KPAD) {
            int n = (int)(i / KPAD), c = (int)(i % KPAD);
            g_xp[i] = (c < FIN) ? x[(size_t)n * FIN + c] : 0.0f;
        }
        return;
    }
    b -= PADB;
    if (b < ZERB) {
        int i = b * 256 + tid;
        if (i <= NN) g_deg[i] = 0;
        return;
    }
    b -= ZERB;
    if (b == 0) {
        __shared__ float we[2][HH][EDIM];
        if (tid < 2 * HH * EDIM) {
            int L = tid >> 7, rem = tid & 127;
            int h = rem / EDIM, c = rem % EDIM;
            const float* line = L ? line1 : line0;
            const float* atte = L ? atte1 : atte0;
            float s = 0.0f;
            for (int d = 0; d < DD; d++)
                s += line[(size_t)c * (HH * DD) + h * DD + d] * atte[h * DD + d];
            we[L][h][c] = s;
        }
        __syncthreads();
        if (tid < 2 * RR * HH) {
            int L = tid / (RR * HH), rem = tid % (RR * HH);
            int r = rem / HH, h = rem % HH;
            float s = 0.0f;
            for (int c = 0; c < EDIM; c++)
                s += rel[r * EDIM + c] * we[L][h][c];
            g_tab[L][r][h] = s;
        }
        if (tid < SCANB) g_scanstate[tid] = 0ULL;
        return;
    }
    b -= 1;
    int idx = b * 256 + tid;                 // [L][h8][k]
    if (idx < 2 * 8 * DD) {
        int L = idx / (8 * DD), rem = idx % (8 * DD);
        int h8 = rem / DD, k = rem % DD;
        const float* lin = L ? lin1 : lin0;
        const float* att;
        int h = h8 & 3;
        if (h8 < 4) att = L ? atts1 : atts0;
        else        att = L ? attd1 : attd0;
        float s = 0.0f;
        for (int d = 0; d < DD; d++)
            s += lin[(size_t)k * (HH * DD) + h * DD + d] * att[h * DD + d];
        g_ws[L][h8][k] = s;
    }
}

__global__ void count_deg(const int* __restrict__ dst) {
    int e = blockIdx.x * blockDim.x + threadIdx.x;
    if (e < EE) atomicAdd(&g_deg[dst[e]], 1);
}

__global__ void scan_lookback() {
    int b = blockIdx.x, tid = threadIdx.x;     // 128 threads
    int lane = tid & 31, warp = tid >> 5;
    int i = b * 128 + tid;
    int v = (i < NN) ? g_deg[i] : 0;
    int incl = v;
#pragma unroll
    for (int o = 1; o < 32; o <<= 1) {
        int t = __shfl_up_sync(0xffffffffu, incl, o);
        if (lane >= o) incl += t;
    }
    __shared__ int wsum[4];
    __shared__ int s_prev;
    if (lane == 31) wsum[warp] = incl;
    __syncthreads();
    int wbase = 0;
    for (int w = 0; w < warp; w++) wbase += wsum[w];
    int incl_b = wbase + incl;
    int total = wsum[0] + wsum[1] + wsum[2] + wsum[3];

    if (tid == 0) {
        if (b == 0) {
            atomicExch(&g_scanstate[0], (2ULL << 32) | (unsigned)total);
            s_prev = 0;
        } else {
            atomicExch(&g_scanstate[b], (1ULL << 32) | (unsigned)total);
            long long run = 0;
            int j = b - 1;
            while (1) {
                unsigned long long st;
                do { st = atomicOr(&g_scanstate[j], 0ULL); } while ((st >> 32) == 0ULL);
                run += (long long)(st & 0xffffffffULL);
                if ((st >> 32) == 2ULL) break;
                j--;
            }
            s_prev = (int)run;
            atomicExch(&g_scanstate[b], (2ULL << 32) | (unsigned)(run + total));
        }
    }
    __syncthreads();
    int excl = s_prev + incl_b - v;
    if (i < NN) {
        g_off[i] = excl;
        g_cur[i] = excl;
        if (i == NN - 1) g_off[NN] = excl + v;
    }
}

__global__ void scatter_csr(const int* __restrict__ dst) {
    int e = blockIdx.x * blockDim.x + threadIdx.x;
    if (e >= EE) return;
    int pos = atomicAdd(&g_cur[dst[e]], 1);
    g_eid[pos] = e;
}

// ---------------- fp16 tensor-core GEMM (m16n8k16 + ldmatrix) ----------------
__device__ __forceinline__ uint32_t h2u(__half2 h) {
    return *reinterpret_cast<uint32_t*>(&h);
}
__device__ __forceinline__ void ldsm_x4(uint32_t* r, uint32_t addr) {
    asm volatile("ldmatrix.sync.aligned.m8n8.x4.shared.b16 {%0,%1,%2,%3}, [%4];"
                 : "=r"(r[0]), "=r"(r[1]), "=r"(r[2]), "=r"(r[3]) : "r"(addr));
}
__device__ __forceinline__ void ldsm_x4_t(uint32_t* r, uint32_t addr) {
    asm volatile("ldmatrix.sync.aligned.m8n8.x4.trans.shared.b16 {%0,%1,%2,%3}, [%4];"
                 : "=r"(r[0]), "=r"(r[1]), "=r"(r[2]), "=r"(r[3]) : "r"(addr));
}
__device__ __forceinline__ void hmma(float* c, const uint32_t* a, uint32_t b0, uint32_t b1) {
    asm volatile(
        "mma.sync.aligned.m16n8k16.row.col.f32.f16.f16.f32 "
        "{%0,%1,%2,%3}, {%4,%5,%6,%7}, {%8,%9}, {%0,%1,%2,%3};\n"
        : "+f"(c[0]), "+f"(c[1]), "+f"(c[2]), "+f"(c[3])
        : "r"(a[0]), "r"(a[1]), "r"(a[2]), "r"(a[3]), "r"(b0), "r"(b1));
}

#define ASTRIDE 24
#define BSTRIDE 136

__global__ __launch_bounds__(256, 2)
void mma_gemm(const float* __restrict__ A, const float* __restrict__ B,
              const float* __restrict__ bias, void* __restrict__ C,
              int M, int K, int KB, int Nn, int doRelu, int doHalf) {
    __shared__ __half As[2][128][ASTRIDE];
    __shared__ __half Bs[2][16][BSTRIDE];
    const int tid = threadIdx.x;
    const int warp = tid >> 5, lane = tid & 31;
    const int g = lane >> 2, tg = lane & 3;
    const int warpM = warp >> 1, warpN = warp & 1;        // 4x2 warps, warp tile 32x64
    const int rowBase = blockIdx.y * 128, colBase = blockIdx.x * 128;

    // stage-load indices
    const int arow = tid >> 1, acol = (tid & 1) * 8;      // A: row, k-offset (8 halfs)
    const int brow = tid >> 4, bcol = (tid & 15) * 8;     // B: k-row, n-offset (8 halfs)

    // ldmatrix lane addressing
    const int lm_row = ((lane >> 3) & 1) * 8 + (lane & 7);
    const int lm_hi  = (lane >= 16) ? 8 : 0;

    float acc[2][8][4];
#pragma unroll
    for (int mi = 0; mi < 2; mi++)
#pragma unroll
        for (int ni = 0; ni < 8; ni++)
#pragma unroll
            for (int r = 0; r < 4; r++) acc[mi][ni][r] = 0.0f;

    const int nk = K / 16;

#define LOAD_TILES(BUF, K0)                                                         \
    {                                                                               \
        int grow = rowBase + arow;                                                  \
        float4 v0 = make_float4(0.f, 0.f, 0.f, 0.f);                                \
        float4 v1 = make_float4(0.f, 0.f, 0.f, 0.f);                                \
        if (grow < M) {                                                             \
            const float* ap = A + (size_t)grow * K + (K0) + acol;                   \
            v0 = *(const float4*)ap;                                                \
            v1 = *(const float4*)(ap + 4);                                          \
        }                                                                           \
        __half2 h0 = __floats2half2_rn(v0.x, v0.y);                                 \
        __half2 h1 = __floats2half2_rn(v0.z, v0.w);                                 \
        __half2 h2 = __floats2half2_rn(v1.x, v1.y);                                 \
        __half2 h3 = __floats2half2_rn(v1.z, v1.w);                                 \
        *(uint4*)&As[BUF][arow][acol] =                                             \
            make_uint4(h2u(h0), h2u(h1), h2u(h2), h2u(h3));                         \
        int kr = (K0) + brow;                                                       \
        float4 w0 = make_float4(0.f, 0.f, 0.f, 0.f);                                \
        float4 w1 = make_float4(0.f, 0.f, 0.f, 0.f);                                \
        if (kr < KB) {                                                              \
            const float* bp = B + (size_t)kr * Nn + colBase + bcol;                 \
            w0 = *(const float4*)bp;                                                \
            w1 = *(const float4*)(bp + 4);                                          \
        }                                                                           \
        __half2 q0 = __floats2half2_rn(w0.x, w0.y);                                 \
        __half2 q1 = __floats2half2_rn(w0.z, w0.w);                                 \
        __half2 q2 = __floats2half2_rn(w1.x, w1.y);                                 \
        __half2 q3 = __floats2half2_rn(w1.z, w1.w);                                 \
        *(uint4*)&Bs[BUF][brow][bcol] =                                             \
            make_uint4(h2u(q0), h2u(q1), h2u(q2), h2u(q3));                         \
    }

    LOAD_TILES(0, 0)
    __syncthreads();

    for (int t = 0; t < nk; t++) {
        int buf = t & 1;
        if (t + 1 < nk) LOAD_TILES(buf ^ 1, (t + 1) * 16)

        // fragments via ldmatrix
        uint32_t a[2][4];
#pragma unroll
        for (int mi = 0; mi < 2; mi++) {
            int row = warpM * 32 + mi * 16 + lm_row;
            uint32_t addr = (uint32_t)__cvta_generic_to_shared(&As[buf][row][lm_hi]);
            ldsm_x4(a[mi], addr);
        }
        uint32_t bf[4][4];
#pragma unroll
        for (int nj = 0; nj < 4; nj++) {
            int nc = warpN * 64 + nj * 16 + lm_hi;
            uint32_t addr = (uint32_t)__cvta_generic_to_shared(&Bs[buf][lm_row][nc]);
            ldsm_x4_t(bf[nj], addr);
        }
#pragma unroll
        for (int ni = 0; ni < 8; ni++) {
            uint32_t b0 = bf[ni >> 1][(ni & 1) * 2];
            uint32_t b1 = bf[ni >> 1][(ni & 1) * 2 + 1];
#pragma unroll
            for (int mi = 0; mi < 2; mi++)
                hmma(acc[mi][ni], a[mi], b0, b1);
        }
        __syncthreads();
    }

#pragma unroll
    for (int mi = 0; mi < 2; mi++) {
        int r0 = rowBase + warpM * 32 + mi * 16 + g;
#pragma unroll
        for (int ni = 0; ni < 8; ni++) {
            int c0 = colBase + warpN * 64 + ni * 8 + tg * 2;
            float bb0 = bias ? bias[c0] : 0.0f;
            float bb1 = bias ? bias[c0 + 1] : 0.0f;
            float v0 = acc[mi][ni][0] + bb0;
            float v1 = acc[mi][ni][1] + bb1;
            float v2 = acc[mi][ni][2] + bb0;
            float v3 = acc[mi][ni][3] + bb1;
            if (doRelu) {
                v0 = fmaxf(v0, 0.f); v1 = fmaxf(v1, 0.f);
                v2 = fmaxf(v2, 0.f); v3 = fmaxf(v3, 0.f);
            }
            if (doHalf) {
                __half* Ch = (__half*)C;
                if (r0 < M) {
                    __half2 p = __floats2half2_rn(v0, v1);
                    *(__half2*)(Ch + (size_t)r0 * Nn + c0) = p;
                }
                if (r0 + 8 < M) {
                    __half2 p = __floats2half2_rn(v2, v3);
                    *(__half2*)(Ch + (size_t)(r0 + 8) * Nn + c0) = p;
                }
            } else {
                float* Cf = (float*)C;
                if (r0 < M) {
                    Cf[(size_t)r0 * Nn + c0] = v0;
                    Cf[(size_t)r0 * Nn + c0 + 1] = v1;
                }
                if (r0 + 8 < M) {
                    Cf[(size_t)(r0 + 8) * Nn + c0] = v2;
                    Cf[(size_t)(r0 + 8) * Nn + c0 + 1] = v3;
                }
            }
        }
    }
#undef LOAD_TILES
}

// ---------------- a_s/a_d for layer 0 from g_x (warp per node) ----------------
__global__ void asd0() {
    int n = blockIdx.x * 8 + (threadIdx.x >> 5);
    int lane = threadIdx.x & 31;
    if (n >= NN) return;
    float4 xv = *(const float4*)(g_x + (size_t)n * DD + lane * 4);
    float r[8];
#pragma unroll
    for (int h = 0; h < 8; h++) {
        const float* w = &g_ws[0][h][lane * 4];
        float p = xv.x * w[0] + xv.y * w[1] + xv.z * w[2] + xv.w * w[3];
#pragma unroll
        for (int o = 16; o; o >>= 1) p += __shfl_xor_sync(0xffffffffu, p, o);
        r[h] = p;
    }
    if (lane < 8) g_asd[0][n * 8 + lane] = r[lane];
}

// fused: on-the-fly alpha + single-pass softmax + aggregate + head-mean + bias + relu
__global__ void gat_node(const int* __restrict__ src, const int* __restrict__ et,
                         const float* __restrict__ bias, float* __restrict__ out, int L) {
    int n = blockIdx.x;
    int tid = threadIdx.x;      // 128
    __shared__ float tab_sm[RR * HH];
    __shared__ float sbuf[512];
    if (tid < RR * HH) tab_sm[tid] = ((const float*)g_tab)[L * RR * HH + tid];
    __syncthreads();

    const float* asd = g_asd[L];
    int p0 = g_off[n], p1 = g_off[n + 1];
    int deg = p1 - p0;
    int head = tid >> 5;
    float adn = asd[n * 8 + 4 + head];

    const uint2* hrow_base = (const uint2*)g_hHh;   // 8B = 4 halfs per thread
    float4 acc = make_float4(0.f, 0.f, 0.f, 0.f);
    float wsum = 0.0f, tsum = 0.0f;

    int p = p0;
    for (; p + 2 <= p1; p += 2) {
        int eid0 = g_eid[p], eid1 = g_eid[p + 1];
        int s0 = src[eid0], s1 = src[eid1];
        int t0 = et[eid0], t1 = et[eid1];
        float tb0 = tab_sm[t0 * HH + head];
        float tb1 = tab_sm[t1 * HH + head];
        float r0 = asd[s0 * 8 + head] + adn + tb0;
        float r1 = asd[s1 * 8 + head] + adn + tb1;
        uint2 u0 = hrow_base[(size_t)s0 * 128 + tid];
        uint2 u1 = hrow_base[(size_t)s1 * 128 + tid];
        r0 = r0 > 0.f ? r0 : 0.2f * r0;
        r1 = r1 > 0.f ? r1 : 0.2f * r1;
        float w0 = __expf(r0), w1 = __expf(r1);
        wsum += w0 + w1;
        tsum += tb0 + tb1;
        float2 f00 = __half22float2(*(__half2*)&u0.x);
        float2 f01 = __half22float2(*(__half2*)&u0.y);
        float2 f10 = __half22float2(*(__half2*)&u1.x);
        float2 f11 = __half22float2(*(__half2*)&u1.y);
        acc.x += w0 * f00.x + w1 * f10.x;
        acc.y += w0 * f00.y + w1 * f10.y;
        acc.z += w0 * f01.x + w1 * f11.x;
        acc.w += w0 * f01.y + w1 * f11.y;
    }
    if (p < p1) {
        int eid = g_eid[p];
        int s = src[eid], t = et[eid];
        float tb = tab_sm[t * HH + head];
        float r = asd[s * 8 + head] + adn + tb;
        r = r > 0.f ? r : 0.2f * r;
        float w = __expf(r);
        wsum += w; tsum += tb;
        uint2 u = hrow_base[(size_t)s * 128 + tid];
        float2 f0 = __half22float2(*(__half2*)&u.x);
        float2 f1 = __half22float2(*(__half2*)&u.y);
        acc.x += w * f0.x; acc.y += w * f0.y;
        acc.z += w * f1.x; acc.w += w * f1.y;
    }
    // self loop
    {
        float asn = asd[n * 8 + head];
        float sr = asn + adn + tsum / fmaxf((float)deg, 1.0f);
        sr = sr > 0.f ? sr : 0.2f * sr;
        float wself = __expf(sr);
        uint2 u = hrow_base[(size_t)n * 128 + tid];
        float2 f0 = __half22float2(*(__half2*)&u.x);
        float2 f1 = __half22float2(*(__half2*)&u.y);
        acc.x += wself * f0.x; acc.y += wself * f0.y;
        acc.z += wself * f1.x; acc.w += wself * f1.y;
        float inv = 1.0f / (wsum + wself + 1e-16f);
        acc.x *= inv; acc.y *= inv; acc.z *= inv; acc.w *= inv;
    }
    *(float4*)&sbuf[tid * 4] = acc;
    __syncthreads();
    if (tid < 32) {
        float ov[4];
#pragma unroll
        for (int j = 0; j < 4; j++) {
            int d = tid * 4 + j;
            float v = 0.25f * (sbuf[d] + sbuf[128 + d] + sbuf[256 + d] + sbuf[384 + d]) + bias[d];
            v = fmaxf(v, 0.0f);
            ov[j] = v;
            out[(size_t)n * 128 + d] = v;
        }
        if (L == 0) {
            float r[8];
#pragma unroll
            for (int h = 0; h < 8; h++) {
                const float* w = &g_ws[1][h][tid * 4];
                float pp = ov[0] * w[0] + ov[1] * w[1] + ov[2] * w[2] + ov[3] * w[3];
#pragma unroll
                for (int o = 16; o; o >>= 1) pp += __shfl_xor_sync(0xffffffffu, pp, o);
                r[h] = pp;
            }
            if (tid < 8) g_asd[1][n * 8 + tid] = r[tid];
        }
    }
}

// ---------------- host ----------------
static float* symaddr(const void* s) {
    void* p = nullptr;
    cudaGetSymbolAddress(&p, s);
    return (float*)p;
}

extern "C" void kernel_launch(void* const* d_in, const int* in_sizes, int n_in,
                              void* d_out, int out_size) {
    const float* x   = (const float*)d_in[0];
    const int*   ei  = (const int*)d_in[1];
    const int*   et  = (const int*)d_in[2];
    const float* w1  = (const float*)d_in[3];
    const float* b1  = (const float*)d_in[4];
    const float* w2  = (const float*)d_in[5];
    const float* b2  = (const float*)d_in[6];
    const float* rel = (const float*)d_in[7];
    const float* lin[2]  = {(const float*)d_in[8],  (const float*)d_in[14]};
    const float* line[2] = {(const float*)d_in[9],  (const float*)d_in[15]};
    const float* atts[2] = {(const float*)d_in[10], (const float*)d_in[16]};
    const float* attd[2] = {(const float*)d_in[11], (const float*)d_in[17]};
    const float* atte[2] = {(const float*)d_in[12], (const float*)d_in[18]};
    const float* bias[2] = {(const float*)d_in[13], (const float*)d_in[19]};
    const int* srcp = ei;
    const int* dstp = ei + EE;

    float* pxp = symaddr(g_xp);
    float* ph1 = symaddr(g_h1);
    float* px  = symaddr(g_x);
    void*  phH = (void*)symaddr(g_hHh);

    setup<<<PADB + ZERB + 1 + 8, 256>>>(x, rel, line[0], atte[0], line[1], atte[1],
                                        lin[0], atts[0], attd[0], lin[1], atts[1], attd[1]);
    count_deg<<<(EE + 255) / 256, 256>>>(dstp);
    scan_lookback<<<SCANB, 128>>>();
    mma_gemm<<<dim3(HID / 128, (NN + 127) / 128), 256>>>(pxp, w1, b1, ph1, NN, KPAD, FIN, HID, 1, 0);
    scatter_csr<<<(EE + 255) / 256, 256>>>(dstp);
    mma_gemm<<<dim3(DD / 128, (NN + 127) / 128), 256>>>(ph1, w2, b2, px, NN, HID, HID, DD, 0, 0);
    asd0<<<(NN + 7) / 8, 256>>>();

    for (int L = 0; L < 2; L++) {
        mma_gemm<<<dim3((HH * DD) / 128, (NN + 127) / 128), 256>>>(
            px, lin[L], nullptr, phH, NN, DD, DD, HH * DD, 0, 1);
        gat_node<<<NN, 128>>>(srcp, et, bias[L], (L == 0) ? px : (float*)d_out, L);
    }
}

// round 10
// speedup vs baseline: 2.0690x; 1.1968x over previous
#include <cuda_runtime.h>
#include <cuda_fp16.h>
#include <math.h>
#include <stdint.h>

#define NN    20000
#define NPAD  20096            // 157*128
#define EE    320000
#define FIN   518
#define KP1   544              // padded K for GEMM1 (multiple of 32)
#define DD    128
#define EDIM  32
#define HH    4
#define RR    26
#define HID   256
#define SCANB ((NN + 127) / 128)
#define PADB  ((int)(((size_t)NPAD * KP1) / 256))      // 42704 exactly
#define ZERB  ((NN + 256) / 256)
#define C1B   ((KP1 * HID) / 256)                      // w1h: 544
#define C2B   ((HID * DD) / 256)                       // w2h: 128
#define C3B   ((2 * DD * HH * DD) / 256)               // linh: 512

// ---------------- scratch ----------------
__device__ __half g_xp[(size_t)NPAD * KP1];
__device__ __half g_h1h[(size_t)NPAD * HID];
__device__ __half g_xh[(size_t)NPAD * DD];
__device__ __half g_hHh[(size_t)NPAD * HH * DD];
__device__ __half g_w1h[(size_t)KP1 * HID];
__device__ __half g_w2h[(size_t)HID * DD];
__device__ __half g_linh[2][(size_t)DD * HH * DD];
__device__ __align__(16) float g_asd[2][NN * 8];
__device__ __align__(16) float g_tab[2][RR][HH];
__device__ float g_ws[2][8][DD];
__device__ int   g_deg[NN + 1];
__device__ int   g_off[NN + 1];
__device__ int   g_cur[NN];
__device__ int   g_eid[EE];
__device__ unsigned long long g_scanstate[SCANB];

// ---------------- setup ----------------
__global__ void setup(const float* __restrict__ x, const float* __restrict__ rel,
                      const float* __restrict__ line0, const float* __restrict__ atte0,
                      const float* __restrict__ line1, const float* __restrict__ atte1,
                      const float* __restrict__ lin0, const float* __restrict__ atts0,
                      const float* __restrict__ attd0,
                      const float* __restrict__ lin1, const float* __restrict__ atts1,
                      const float* __restrict__ attd1,
                      const float* __restrict__ w1, const float* __restrict__ w2) {
    int b = blockIdx.x, tid = threadIdx.x;
    if (b < PADB) {
        size_t i = (size_t)b * 256 + tid;
        int n = (int)(i / KP1), c = (int)(i % KP1);
        float v = (n < NN && c < FIN) ? x[(size_t)n * FIN + c] : 0.0f;
        g_xp[i] = __float2half(v);
        return;
    }
    b -= PADB;
    if (b < ZERB) {
        int i = b * 256 + tid;
        if (i <= NN) g_deg[i] = 0;
        return;
    }
    b -= ZERB;
    if (b == 0) {
        __shared__ float we[2][HH][EDIM];
        if (tid < 2 * HH * EDIM) {
            int L = tid >> 7, rem = tid & 127;
            int h = rem / EDIM, c = rem % EDIM;
            const float* line = L ? line1 : line0;
            const float* atte = L ? atte1 : atte0;
            float s = 0.0f;
            for (int d = 0; d < DD; d++)
                s += line[(size_t)c * (HH * DD) + h * DD + d] * atte[h * DD + d];
            we[L][h][c] = s;
        }
        __syncthreads();
        if (tid < 2 * RR * HH) {
            int L = tid / (RR * HH), rem = tid % (RR * HH);
            int r = rem / HH, h = rem % HH;
            float s = 0.0f;
            for (int c = 0; c < EDIM; c++)
                s += rel[r * EDIM + c] * we[L][h][c];
            g_tab[L][r][h] = s;
        }
        if (tid < SCANB) g_scanstate[tid] = 0ULL;
        return;
    }
    b -= 1;
    if (b < 8) {
        int idx = b * 256 + tid;                 // [L][h8][k]
        if (idx < 2 * 8 * DD) {
            int L = idx / (8 * DD), rem = idx % (8 * DD);
            int h8 = rem / DD, k = rem % DD;
            const float* lin = L ? lin1 : lin0;
            const float* att;
            int h = h8 & 3;
            if (h8 < 4) att = L ? atts1 : atts0;
            else        att = L ? attd1 : attd0;
            float s = 0.0f;
            for (int d = 0; d < DD; d++)
                s += lin[(size_t)k * (HH * DD) + h * DD + d] * att[h * DD + d];
            g_ws[L][h8][k] = s;
        }
        return;
    }
    b -= 8;
    if (b < C1B) {
        int i = b * 256 + tid;                   // KP1 x HID
        int k = i / HID, n = i % HID;
        g_w1h[i] = __float2half(k < FIN ? w1[(size_t)k * HID + n] : 0.0f);
        return;
    }
    b -= C1B;
    if (b < C2B) {
        int i = b * 256 + tid;
        g_w2h[i] = __float2half(w2[i]);
        return;
    }
    b -= C2B;
    {
        int i = b * 256 + tid;                   // 2 x (DD x 512)
        int L = i / (DD * HH * DD), r = i % (DD * HH * DD);
        const float* lin = L ? lin1 : lin0;
        g_linh[L][r] = __float2half(lin[r]);
    }
}

__global__ void count_deg(const int* __restrict__ dst) {
    int e = blockIdx.x * blockDim.x + threadIdx.x;
    if (e < EE) atomicAdd(&g_deg[dst[e]], 1);
}

__global__ void scan_lookback() {
    int b = blockIdx.x, tid = threadIdx.x;     // 128 threads
    int lane = tid & 31, warp = tid >> 5;
    int i = b * 128 + tid;
    int v = (i < NN) ? g_deg[i] : 0;
    int incl = v;
#pragma unroll
    for (int o = 1; o < 32; o <<= 1) {
        int t = __shfl_up_sync(0xffffffffu, incl, o);
        if (lane >= o) incl += t;
    }
    __shared__ int wsum[4];
    __shared__ int s_prev;
    if (lane == 31) wsum[warp] = incl;
    __syncthreads();
    int wbase = 0;
    for (int w = 0; w < warp; w++) wbase += wsum[w];
    int incl_b = wbase + incl;
    int total = wsum[0] + wsum[1] + wsum[2] + wsum[3];

    if (tid == 0) {
        if (b == 0) {
            atomicExch(&g_scanstate[0], (2ULL << 32) | (unsigned)total);
            s_prev = 0;
        } else {
            atomicExch(&g_scanstate[b], (1ULL << 32) | (unsigned)total);
            long long run = 0;
            int j = b - 1;
            while (1) {
                unsigned long long st;
                do { st = atomicOr(&g_scanstate[j], 0ULL); } while ((st >> 32) == 0ULL);
                run += (long long)(st & 0xffffffffULL);
                if ((st >> 32) == 2ULL) break;
                j--;
            }
            s_prev = (int)run;
            atomicExch(&g_scanstate[b], (2ULL << 32) | (unsigned)(run + total));
        }
    }
    __syncthreads();
    int excl = s_prev + incl_b - v;
    if (i < NN) {
        g_off[i] = excl;
        g_cur[i] = excl;
        if (i == NN - 1) g_off[NN] = excl + v;
    }
}

__global__ void scatter_csr(const int* __restrict__ dst) {
    int e = blockIdx.x * blockDim.x + threadIdx.x;
    if (e >= EE) return;
    int pos = atomicAdd(&g_cur[dst[e]], 1);
    g_eid[pos] = e;
}

// ---------------- fp16 tensor-core GEMM (cp.async 4-stage + ldmatrix + m16n8k16) ----------------
__device__ __forceinline__ uint32_t h2u(__half2 h) {
    return *reinterpret_cast<uint32_t*>(&h);
}
__device__ __forceinline__ void ldsm_x4(uint32_t* r, uint32_t addr) {
    asm volatile("ldmatrix.sync.aligned.m8n8.x4.shared.b16 {%0,%1,%2,%3}, [%4];"
                 : "=r"(r[0]), "=r"(r[1]), "=r"(r[2]), "=r"(r[3]) : "r"(addr));
}
__device__ __forceinline__ void ldsm_x4_t(uint32_t* r, uint32_t addr) {
    asm volatile("ldmatrix.sync.aligned.m8n8.x4.trans.shared.b16 {%0,%1,%2,%3}, [%4];"
                 : "=r"(r[0]), "=r"(r[1]), "=r"(r[2]), "=r"(r[3]) : "r"(addr));
}
__device__ __forceinline__ void hmma(float* c, const uint32_t* a, uint32_t b0, uint32_t b1) {
    asm volatile(
        "mma.sync.aligned.m16n8k16.row.col.f32.f16.f16.f32 "
        "{%0,%1,%2,%3}, {%4,%5,%6,%7}, {%8,%9}, {%0,%1,%2,%3};\n"
        : "+f"(c[0]), "+f"(c[1]), "+f"(c[2]), "+f"(c[3])
        : "r"(a[0]), "r"(a[1]), "r"(a[2]), "r"(a[3]), "r"(b0), "r"(b1));
}
__device__ __forceinline__ void cp16(uint32_t dst, const void* src) {
    asm volatile("cp.async.cg.shared.global [%0], [%1], 16;" :: "r"(dst), "l"(src));
}
__device__ __forceinline__ void cp_commit() {
    asm volatile("cp.async.commit_group;" ::: "memory");
}
__device__ __forceinline__ void cp_wait2() {
    asm volatile("cp.async.wait_group 2;" ::: "memory");
}

#define STAGES   4
#define A_STAGE  10240       // 128 rows * 80 B
#define B_STAGE  8704        // 32 rows * 272 B
#define SMEM_SZ  (STAGES * (A_STAGE + B_STAGE))   // 75776

__global__ __launch_bounds__(256)
void mma_gemm(const __half* __restrict__ A, const __half* __restrict__ B,
              const float* __restrict__ bias, __half* __restrict__ C,
              int K, int Nn, int doRelu) {
    extern __shared__ char smem[];
    const uint32_t smem_u = (uint32_t)__cvta_generic_to_shared(smem);
    const uint32_t as_u = smem_u;
    const uint32_t bs_u = smem_u + STAGES * A_STAGE;

    const int tid = threadIdx.x;
    const int warp = tid >> 5, lane = tid & 31;
    const int g = lane >> 2, tg = lane & 3;
    const int warpM = warp >> 1, warpN = warp & 1;        // 4x2 warps, warp tile 32x64
    const int rowBase = blockIdx.y * 128, colBase = blockIdx.x * 128;

    // cp.async mappings
    const int a_row = tid >> 1, a_ch = (tid & 1) * 2;     // A: 2 chunks of 16B each
    const uint32_t a_dst = as_u + a_row * 80 + a_ch * 16;
    const __half* a_src = A + (size_t)(rowBase + a_row) * K + a_ch * 8;
    const int b_row = tid >> 3, b_ch = (tid & 7) * 2;     // B: 2 chunks of 16B each
    const uint32_t b_dst = bs_u + b_row * 272 + b_ch * 16;
    const __half* b_src = B + (size_t)b_row * Nn + colBase + b_ch * 8;

    // ldmatrix lane addressing
    const int lm_row = ((lane >> 3) & 1) * 8 + (lane & 7);
    const int lm_hi  = (lane >= 16) ? 8 : 0;

    float acc[2][8][4];
#pragma unroll
    for (int mi = 0; mi < 2; mi++)
#pragma unroll
        for (int ni = 0; ni < 8; ni++)
#pragma unroll
            for (int r = 0; r < 4; r++) acc[mi][ni][r] = 0.0f;

    const int nk = K / 32;

#define ISSUE(S, T)                                                        \
    {                                                                      \
        int k0 = (T) * 32;                                                 \
        cp16(a_dst + (S) * A_STAGE, a_src + k0);                           \
        cp16(a_dst + (S) * A_STAGE + 16, a_src + k0 + 8);                  \
        cp16(b_dst + (S) * B_STAGE, b_src + (size_t)k0 * Nn);              \
        cp16(b_dst + (S) * B_STAGE + 16, b_src + (size_t)k0 * Nn + 8);     \
    }

    // prologue: stages 0..2
#pragma unroll
    for (int s = 0; s < STAGES - 1; s++) {
        if (s < nk) ISSUE(s, s)
        cp_commit();
    }

    for (int t = 0; t < nk; t++) {
        cp_wait2();
        __syncthreads();
        // issue stage t+3
        if (t + STAGES - 1 < nk) ISSUE((t + STAGES - 1) & 3, t + STAGES - 1)
        cp_commit();

        const uint32_t as_s = as_u + (t & 3) * A_STAGE;
        const uint32_t bs_s = bs_u + (t & 3) * B_STAGE;
#pragma unroll
        for (int ks = 0; ks < 2; ks++) {
            uint32_t a[2][4];
#pragma unroll
            for (int mi = 0; mi < 2; mi++) {
                int row = warpM * 32 + mi * 16 + lm_row;
                ldsm_x4(a[mi], as_s + row * 80 + (ks * 16 + lm_hi) * 2);
            }
            uint32_t bf[4][4];
#pragma unroll
            for (int nj = 0; nj < 4; nj++) {
                int col = warpN * 64 + nj * 16 + lm_hi;
                ldsm_x4_t(bf[nj], bs_s + (ks * 16 + lm_row) * 272 + col * 2);
            }
#pragma unroll
            for (int ni = 0; ni < 8; ni++) {
                uint32_t b0 = bf[ni >> 1][(ni & 1) * 2];
                uint32_t b1 = bf[ni >> 1][(ni & 1) * 2 + 1];
#pragma unroll
                for (int mi = 0; mi < 2; mi++)
                    hmma(acc[mi][ni], a[mi], b0, b1);
            }
        }
    }
#undef ISSUE

    // epilogue (C padded to NPAD rows; no guards)
#pragma unroll
    for (int mi = 0; mi < 2; mi++) {
        int r0 = rowBase + warpM * 32 + mi * 16 + g;
#pragma unroll
        for (int ni = 0; ni < 8; ni++) {
            int c0 = colBase + warpN * 64 + ni * 8 + tg * 2;
            float bb0 = bias ? bias[c0] : 0.0f;
            float bb1 = bias ? bias[c0 + 1] : 0.0f;
            float v0 = acc[mi][ni][0] + bb0;
            float v1 = acc[mi][ni][1] + bb1;
            float v2 = acc[mi][ni][2] + bb0;
            float v3 = acc[mi][ni][3] + bb1;
            if (doRelu) {
                v0 = fmaxf(v0, 0.f); v1 = fmaxf(v1, 0.f);
                v2 = fmaxf(v2, 0.f); v3 = fmaxf(v3, 0.f);
            }
            __half2 p0 = __floats2half2_rn(v0, v1);
            __half2 p1 = __floats2half2_rn(v2, v3);
            *(uint32_t*)(C + (size_t)r0 * Nn + c0) = h2u(p0);
            *(uint32_t*)(C + (size_t)(r0 + 8) * Nn + c0) = h2u(p1);
        }
    }
}

// ---------------- a_s/a_d for layer 0 from g_xh (warp per node) ----------------
__global__ void asd0() {
    int n = blockIdx.x * 8 + (threadIdx.x >> 5);
    int lane = threadIdx.x & 31;
    if (n >= NN) return;
    uint2 u = *(const uint2*)(g_xh + (size_t)n * DD + lane * 4);
    float2 xa = __half22float2(*(__half2*)&u.x);
    float2 xb = __half22float2(*(__half2*)&u.y);
    float r[8];
#pragma unroll
    for (int h = 0; h < 8; h++) {
        const float* w = &g_ws[0][h][lane * 4];
        float p = xa.x * w[0] + xa.y * w[1] + xb.x * w[2] + xb.y * w[3];
#pragma unroll
        for (int o = 16; o; o >>= 1) p += __shfl_xor_sync(0xffffffffu, p, o);
        r[h] = p;
    }
    if (lane < 8) g_asd[0][n * 8 + lane] = r[lane];
}

// fused: on-the-fly alpha + single-pass softmax + aggregate + head-mean + bias + relu
__global__ void gat_node(const int* __restrict__ src, const int* __restrict__ et,
                         const float* __restrict__ bias, float* __restrict__ outF, int L) {
    int n = blockIdx.x;
    int tid = threadIdx.x;      // 128
    __shared__ float tab_sm[RR * HH];
    __shared__ float sbuf[512];
    if (tid < RR * HH) tab_sm[tid] = ((const float*)g_tab)[L * RR * HH + tid];
    __syncthreads();

    const float* asd = g_asd[L];
    int p0 = g_off[n], p1 = g_off[n + 1];
    int deg = p1 - p0;
    int head = tid >> 5;
    float adn = asd[n * 8 + 4 + head];

    const uint2* hrow_base = (const uint2*)g_hHh;
    float4 acc = make_float4(0.f, 0.f, 0.f, 0.f);
    float wsum = 0.0f, tsum = 0.0f;

    int p = p0;
    for (; p + 2 <= p1; p += 2) {
        int eid0 = g_eid[p], eid1 = g_eid[p + 1];
        int s0 = src[eid0], s1 = src[eid1];
        int t0 = et[eid0], t1 = et[eid1];
        float tb0 = tab_sm[t0 * HH + head];
        float tb1 = tab_sm[t1 * HH + head];
        float r0 = asd[s0 * 8 + head] + adn + tb0;
        float r1 = asd[s1 * 8 + head] + adn + tb1;
        uint2 u0 = hrow_base[(size_t)s0 * 128 + tid];
        uint2 u1 = hrow_base[(size_t)s1 * 128 + tid];
        r0 = r0 > 0.f ? r0 : 0.2f * r0;
        r1 = r1 > 0.f ? r1 : 0.2f * r1;
        float w0 = __expf(r0), w1 = __expf(r1);
        wsum += w0 + w1;
        tsum += tb0 + tb1;
        float2 f00 = __half22float2(*(__half2*)&u0.x);
        float2 f01 = __half22float2(*(__half2*)&u0.y);
        float2 f10 = __half22float2(*(__half2*)&u1.x);
        float2 f11 = __half22float2(*(__half2*)&u1.y);
        acc.x += w0 * f00.x + w1 * f10.x;
        acc.y += w0 * f00.y + w1 * f10.y;
        acc.z += w0 * f01.x + w1 * f11.x;
        acc.w += w0 * f01.y + w1 * f11.y;
    }
    if (p < p1) {
        int eid = g_eid[p];
        int s = src[eid], t = et[eid];
        float tb = tab_sm[t * HH + head];
        float r = asd[s * 8 + head] + adn + tb;
        r = r > 0.f ? r : 0.2f * r;
        float w = __expf(r);
        wsum += w; tsum += tb;
        uint2 u = hrow_base[(size_t)s * 128 + tid];
        float2 f0 = __half22float2(*(__half2*)&u.x);
        float2 f1 = __half22float2(*(__half2*)&u.y);
        acc.x += w * f0.x; acc.y += w * f0.y;
        acc.z += w * f1.x; acc.w += w * f1.y;
    }
    // self loop
    {
        float asn = asd[n * 8 + head];
        float sr = asn + adn + tsum / fmaxf((float)deg, 1.0f);
        sr = sr > 0.f ? sr : 0.2f * sr;
        float wself = __expf(sr);
        uint2 u = hrow_base[(size_t)n * 128 + tid];
        float2 f0 = __half22float2(*(__half2*)&u.x);
        float2 f1 = __half22float2(*(__half2*)&u.y);
        acc.x += wself * f0.x; acc.y += wself * f0.y;
        acc.z += wself * f1.x; acc.w += wself * f1.y;
        float inv = 1.0f / (wsum + wself + 1e-16f);
        acc.x *= inv; acc.y *= inv; acc.z *= inv; acc.w *= inv;
    }
    *(float4*)&sbuf[tid * 4] = acc;
    __syncthreads();
    if (tid < 32) {
        float ov[4];
#pragma unroll
        for (int j = 0; j < 4; j++) {
            int d = tid * 4 + j;
            float v = 0.25f * (sbuf[d] + sbuf[128 + d] + sbuf[256 + d] + sbuf[384 + d]) + bias[d];
            v = fmaxf(v, 0.0f);
            ov[j] = v;
        }
        if (L == 0) {
            // half output for next GEMM
            __half2 p0 = __floats2half2_rn(ov[0], ov[1]);
            __half2 p1 = __floats2half2_rn(ov[2], ov[3]);
            uint2 pk = make_uint2(h2u(p0), h2u(p1));
            *(uint2*)(g_xh + (size_t)n * DD + tid * 4) = pk;
            // next-layer a_s/a_d into slot 1
            float r[8];
#pragma unroll
            for (int h = 0; h < 8; h++) {
                const float* w = &g_ws[1][h][tid * 4];
                float pp = ov[0] * w[0] + ov[1] * w[1] + ov[2] * w[2] + ov[3] * w[3];
#pragma unroll
                for (int o = 16; o; o >>= 1) pp += __shfl_xor_sync(0xffffffffu, pp, o);
                r[h] = pp;
            }
            if (tid < 8) g_asd[1][n * 8 + tid] = r[tid];
        } else {
#pragma unroll
            for (int j = 0; j < 4; j++)
                outF[(size_t)n * DD + tid * 4 + j] = ov[j];
        }
    }
}

// ---------------- host ----------------
template <typename T>
static T* symaddr(const void* s) {
    void* p = nullptr;
    cudaGetSymbolAddress(&p, s);
    return (T*)p;
}

extern "C" void kernel_launch(void* const* d_in, const int* in_sizes, int n_in,
                              void* d_out, int out_size) {
    const float* x   = (const float*)d_in[0];
    const int*   ei  = (const int*)d_in[1];
    const int*   et  = (const int*)d_in[2];
    const float* w1  = (const float*)d_in[3];
    const float* b1  = (const float*)d_in[4];
    const float* w2  = (const float*)d_in[5];
    const float* b2  = (const float*)d_in[6];
    const float* rel = (const float*)d_in[7];
    const float* lin[2]  = {(const float*)d_in[8],  (const float*)d_in[14]};
    const float* line[2] = {(const float*)d_in[9],  (const float*)d_in[15]};
    const float* atts[2] = {(const float*)d_in[10], (const float*)d_in[16]};
    const float* attd[2] = {(const float*)d_in[11], (const float*)d_in[17]};
    const float* atte[2] = {(const float*)d_in[12], (const float*)d_in[18]};
    const float* bias[2] = {(const float*)d_in[13], (const float*)d_in[19]};
    const int* srcp = ei;
    const int* dstp = ei + EE;

    __half* pxp  = symaddr<__half>(g_xp);
    __half* ph1  = symaddr<__half>(g_h1h);
    __half* pxh  = symaddr<__half>(g_xh);
    __half* phH  = symaddr<__half>(g_hHh);
    __half* pw1  = symaddr<__half>(g_w1h);
    __half* pw2  = symaddr<__half>(g_w2h);
    __half* pl0  = symaddr<__half>(g_linh);
    __half* pl1  = pl0 + (size_t)DD * HH * DD;

    cudaFuncSetAttribute(mma_gemm, cudaFuncAttributeMaxDynamicSharedMemorySize, SMEM_SZ);

    setup<<<PADB + ZERB + 1 + 8 + C1B + C2B + C3B, 256>>>(
        x, rel, line[0], atte[0], line[1], atte[1],
        lin[0], atts[0], attd[0], lin[1], atts[1], attd[1], w1, w2);
    count_deg<<<(EE + 255) / 256, 256>>>(dstp);
    scan_lookback<<<SCANB, 128>>>();
    mma_gemm<<<dim3(HID / 128, NPAD / 128), 256, SMEM_SZ>>>(pxp, pw1, b1, ph1, KP1, HID, 1);
    scatter_csr<<<(EE + 255) / 256, 256>>>(dstp);
    mma_gemm<<<dim3(DD / 128, NPAD / 128), 256, SMEM_SZ>>>(ph1, pw2, b2, pxh, HID, DD, 0);
    asd0<<<(NN + 7) / 8, 256>>>();

    for (int L = 0; L < 2; L++) {
        mma_gemm<<<dim3((HH * DD) / 128, NPAD / 128), 256, SMEM_SZ>>>(
            pxh, L ? pl1 : pl0, nullptr, phH, DD, HH * DD, 0);
        gat_node<<<NN, 128>>>(srcp, et, bias[L], (float*)d_out, L);
    }
}

// round 11
// speedup vs baseline: 2.3545x; 1.1380x over previous
#include <cuda_runtime.h>
#include <cuda_fp16.h>
#include <math.h>
#include <stdint.h>

#define NN    20000
#define NPAD  20096            // 157*128
#define EE    320000
#define FIN   518
#define KP1   544              // padded K for GEMM1 (multiple of 32)
#define DD    128
#define EDIM  32
#define HH    4
#define RR    26
#define HID   256
#define SCANB ((NN + 127) / 128)
#define PADB  ((int)(((size_t)NPAD * KP1) / 256))      // exact
#define ZERB  ((NN + 256) / 256)
#define C1B   ((KP1 * HID) / 256)
#define C2B   ((HID * DD) / 256)
#define C3B   ((2 * DD * HH * DD) / 256)

// ---------------- scratch ----------------
__device__ __half g_xp[(size_t)NPAD * KP1];
__device__ __half g_h1h[(size_t)NPAD * HID];
__device__ __half g_xh[(size_t)NPAD * DD];
__device__ __half g_hHh[(size_t)NPAD * HH * DD];
__device__ __half g_w1h[(size_t)KP1 * HID];
__device__ __half g_w2h[(size_t)HID * DD];
__device__ __half g_linh[2][(size_t)DD * HH * DD];
__device__ __align__(16) float g_asd[2][NN * 8];
__device__ __align__(16) float g_tab[2][RR][HH];
__device__ float g_ws[2][8][DD];
__device__ int   g_deg[NN + 1];
__device__ int   g_off[NN + 1];
__device__ int   g_cur[NN];
__device__ int   g_esd[EE];          // packed: src | (et << 20)
__device__ unsigned long long g_scanstate[SCANB];

// ---------------- setup ----------------
__global__ void setup(const float* __restrict__ x, const float* __restrict__ rel,
                      const float* __restrict__ line0, const float* __restrict__ atte0,
                      const float* __restrict__ line1, const float* __restrict__ atte1,
                      const float* __restrict__ lin0, const float* __restrict__ atts0,
                      const float* __restrict__ attd0,
                      const float* __restrict__ lin1, const float* __restrict__ atts1,
                      const float* __restrict__ attd1,
                      const float* __restrict__ w1, const float* __restrict__ w2) {
    int b = blockIdx.x, tid = threadIdx.x;
    if (b < PADB) {
        size_t i = (size_t)b * 256 + tid;
        int n = (int)(i / KP1), c = (int)(i % KP1);
        float v = (n < NN && c < FIN) ? x[(size_t)n * FIN + c] : 0.0f;
        g_xp[i] = __float2half(v);
        return;
    }
    b -= PADB;
    if (b < ZERB) {
        int i = b * 256 + tid;
        if (i <= NN) g_deg[i] = 0;
        return;
    }
    b -= ZERB;
    if (b == 0) {
        __shared__ float we[2][HH][EDIM];
        if (tid < 2 * HH * EDIM) {
            int L = tid >> 7, rem = tid & 127;
            int h = rem / EDIM, c = rem % EDIM;
            const float* line = L ? line1 : line0;
            const float* atte = L ? atte1 : atte0;
            float s = 0.0f;
            for (int d = 0; d < DD; d++)
                s += line[(size_t)c * (HH * DD) + h * DD + d] * atte[h * DD + d];
            we[L][h][c] = s;
        }
        __syncthreads();
        if (tid < 2 * RR * HH) {
            int L = tid / (RR * HH), rem = tid % (RR * HH);
            int r = rem / HH, h = rem % HH;
            float s = 0.0f;
            for (int c = 0; c < EDIM; c++)
                s += rel[r * EDIM + c] * we[L][h][c];
            g_tab[L][r][h] = s;
        }
        if (tid < SCANB) g_scanstate[tid] = 0ULL;
        return;
    }
    b -= 1;
    if (b < 8) {
        int idx = b * 256 + tid;                 // [L][h8][k]
        if (idx < 2 * 8 * DD) {
            int L = idx / (8 * DD), rem = idx % (8 * DD);
            int h8 = rem / DD, k = rem % DD;
            const float* lin = L ? lin1 : lin0;
            const float* att;
            int h = h8 & 3;
            if (h8 < 4) att = L ? atts1 : atts0;
            else        att = L ? attd1 : attd0;
            float s = 0.0f;
            for (int d = 0; d < DD; d++)
                s += lin[(size_t)k * (HH * DD) + h * DD + d] * att[h * DD + d];
            g_ws[L][h8][k] = s;
        }
        return;
    }
    b -= 8;
    if (b < C1B) {
        int i = b * 256 + tid;                   // KP1 x HID
        int k = i / HID, n = i % HID;
        g_w1h[i] = __float2half(k < FIN ? w1[(size_t)k * HID + n] : 0.0f);
        return;
    }
    b -= C1B;
    if (b < C2B) {
        int i = b * 256 + tid;
        g_w2h[i] = __float2half(w2[i]);
        return;
    }
    b -= C2B;
    {
        int i = b * 256 + tid;                   // 2 x (DD x 512)
        int L = i / (DD * HH * DD), r = i % (DD * HH * DD);
        const float* lin = L ? lin1 : lin0;
        g_linh[L][r] = __float2half(lin[r]);
    }
}

__global__ void count_deg(const int* __restrict__ dst) {
    int e = blockIdx.x * blockDim.x + threadIdx.x;
    if (e < EE) atomicAdd(&g_deg[dst[e]], 1);
}

__global__ void scan_lookback() {
    int b = blockIdx.x, tid = threadIdx.x;     // 128 threads
    int lane = tid & 31, warp = tid >> 5;
    int i = b * 128 + tid;
    int v = (i < NN) ? g_deg[i] : 0;
    int incl = v;
#pragma unroll
    for (int o = 1; o < 32; o <<= 1) {
        int t = __shfl_up_sync(0xffffffffu, incl, o);
        if (lane >= o) incl += t;
    }
    __shared__ int wsum[4];
    __shared__ int s_prev;
    if (lane == 31) wsum[warp] = incl;
    __syncthreads();
    int wbase = 0;
    for (int w = 0; w < warp; w++) wbase += wsum[w];
    int incl_b = wbase + incl;
    int total = wsum[0] + wsum[1] + wsum[2] + wsum[3];

    if (tid == 0) {
        if (b == 0) {
            atomicExch(&g_scanstate[0], (2ULL << 32) | (unsigned)total);
            s_prev = 0;
        } else {
            atomicExch(&g_scanstate[b], (1ULL << 32) | (unsigned)total);
            long long run = 0;
            int j = b - 1;
            while (1) {
                unsigned long long st;
                do { st = atomicOr(&g_scanstate[j], 0ULL); } while ((st >> 32) == 0ULL);
                run += (long long)(st & 0xffffffffULL);
                if ((st >> 32) == 2ULL) break;
                j--;
            }
            s_prev = (int)run;
            atomicExch(&g_scanstate[b], (2ULL << 32) | (unsigned)(run + total));
        }
    }
    __syncthreads();
    int excl = s_prev + incl_b - v;
    if (i < NN) {
        g_off[i] = excl;
        g_cur[i] = excl;
        if (i == NN - 1) g_off[NN] = excl + v;
    }
}

__global__ void scatter_csr(const int* __restrict__ src, const int* __restrict__ dst,
                            const int* __restrict__ et) {
    int e = blockIdx.x * blockDim.x + threadIdx.x;
    if (e >= EE) return;
    int pos = atomicAdd(&g_cur[dst[e]], 1);
    g_esd[pos] = src[e] | (et[e] << 20);
}

// ---------------- fp16 tensor-core GEMM (cp.async 4-stage + ldmatrix + m16n8k16) ----------------
__device__ __forceinline__ uint32_t h2u(__half2 h) {
    return *reinterpret_cast<uint32_t*>(&h);
}
__device__ __forceinline__ void ldsm_x4(uint32_t* r, uint32_t addr) {
    asm volatile("ldmatrix.sync.aligned.m8n8.x4.shared.b16 {%0,%1,%2,%3}, [%4];"
                 : "=r"(r[0]), "=r"(r[1]), "=r"(r[2]), "=r"(r[3]) : "r"(addr));
}
__device__ __forceinline__ void ldsm_x4_t(uint32_t* r, uint32_t addr) {
    asm volatile("ldmatrix.sync.aligned.m8n8.x4.trans.shared.b16 {%0,%1,%2,%3}, [%4];"
                 : "=r"(r[0]), "=r"(r[1]), "=r"(r[2]), "=r"(r[3]) : "r"(addr));
}
__device__ __forceinline__ void hmma(float* c, const uint32_t* a, uint32_t b0, uint32_t b1) {
    asm volatile(
        "mma.sync.aligned.m16n8k16.row.col.f32.f16.f16.f32 "
        "{%0,%1,%2,%3}, {%4,%5,%6,%7}, {%8,%9}, {%0,%1,%2,%3};\n"
        : "+f"(c[0]), "+f"(c[1]), "+f"(c[2]), "+f"(c[3])
        : "r"(a[0]), "r"(a[1]), "r"(a[2]), "r"(a[3]), "r"(b0), "r"(b1));
}
__device__ __forceinline__ void cp16(uint32_t dst, const void* src) {
    asm volatile("cp.async.cg.shared.global [%0], [%1], 16;" :: "r"(dst), "l"(src));
}
__device__ __forceinline__ void cp_commit() {
    asm volatile("cp.async.commit_group;" ::: "memory");
}
__device__ __forceinline__ void cp_wait2() {
    asm volatile("cp.async.wait_group 2;" ::: "memory");
}

#define STAGES   4
#define A_STAGE  10240       // 128 rows * 80 B
#define B_STAGE  8704        // 32 rows * 272 B
#define SMEM_SZ  (STAGES * (A_STAGE + B_STAGE))   // 75776

__global__ __launch_bounds__(256)
void mma_gemm(const __half* __restrict__ A, const __half* __restrict__ B,
              const float* __restrict__ bias, __half* __restrict__ C,
              int K, int Nn, int doRelu) {
    extern __shared__ char smem[];
    const uint32_t smem_u = (uint32_t)__cvta_generic_to_shared(smem);
    const uint32_t as_u = smem_u;
    const uint32_t bs_u = smem_u + STAGES * A_STAGE;

    const int tid = threadIdx.x;
    const int warp = tid >> 5, lane = tid & 31;
    const int g = lane >> 2, tg = lane & 3;
    const int warpM = warp >> 1, warpN = warp & 1;        // 4x2 warps, warp tile 32x64
    const int rowBase = blockIdx.y * 128, colBase = blockIdx.x * 128;

    const int a_row = tid >> 1, a_ch = (tid & 1) * 2;
    const uint32_t a_dst = as_u + a_row * 80 + a_ch * 16;
    const __half* a_src = A + (size_t)(rowBase + a_row) * K + a_ch * 8;
    const int b_row = tid >> 3, b_ch = (tid & 7) * 2;
    const uint32_t b_dst = bs_u + b_row * 272 + b_ch * 16;
    const __half* b_src = B + (size_t)b_row * Nn + colBase + b_ch * 8;

    const int lm_row = ((lane >> 3) & 1) * 8 + (lane & 7);
    const int lm_hi  = (lane >= 16) ? 8 : 0;

    float acc[2][8][4];
#pragma unroll
    for (int mi = 0; mi < 2; mi++)
#pragma unroll
        for (int ni = 0; ni < 8; ni++)
#pragma unroll
            for (int r = 0; r < 4; r++) acc[mi][ni][r] = 0.0f;

    const int nk = K / 32;

#define ISSUE(S, T)                                                        \
    {                                                                      \
        int k0 = (T) * 32;                                                 \
        cp16(a_dst + (S) * A_STAGE, a_src + k0);                           \
        cp16(a_dst + (S) * A_STAGE + 16, a_src + k0 + 8);                  \
        cp16(b_dst + (S) * B_STAGE, b_src + (size_t)k0 * Nn);              \
        cp16(b_dst + (S) * B_STAGE + 16, b_src + (size_t)k0 * Nn + 8);     \
    }

#pragma unroll
    for (int s = 0; s < STAGES - 1; s++) {
        if (s < nk) ISSUE(s, s)
        cp_commit();
    }

    for (int t = 0; t < nk; t++) {
        cp_wait2();
        __syncthreads();
        if (t + STAGES - 1 < nk) ISSUE((t + STAGES - 1) & 3, t + STAGES - 1)
        cp_commit();

        const uint32_t as_s = as_u + (t & 3) * A_STAGE;
        const uint32_t bs_s = bs_u + (t & 3) * B_STAGE;
#pragma unroll
        for (int ks = 0; ks < 2; ks++) {
            uint32_t a[2][4];
#pragma unroll
            for (int mi = 0; mi < 2; mi++) {
                int row = warpM * 32 + mi * 16 + lm_row;
                ldsm_x4(a[mi], as_s + row * 80 + (ks * 16 + lm_hi) * 2);
            }
            uint32_t bf[4][4];
#pragma unroll
            for (int nj = 0; nj < 4; nj++) {
                int col = warpN * 64 + nj * 16 + lm_hi;
                ldsm_x4_t(bf[nj], bs_s + (ks * 16 + lm_row) * 272 + col * 2);
            }
#pragma unroll
            for (int ni = 0; ni < 8; ni++) {
                uint32_t b0 = bf[ni >> 1][(ni & 1) * 2];
                uint32_t b1 = bf[ni >> 1][(ni & 1) * 2 + 1];
#pragma unroll
                for (int mi = 0; mi < 2; mi++)
                    hmma(acc[mi][ni], a[mi], b0, b1);
            }
        }
    }
#undef ISSUE

#pragma unroll
    for (int mi = 0; mi < 2; mi++) {
        int r0 = rowBase + warpM * 32 + mi * 16 + g;
#pragma unroll
        for (int ni = 0; ni < 8; ni++) {
            int c0 = colBase + warpN * 64 + ni * 8 + tg * 2;
            float bb0 = bias ? bias[c0] : 0.0f;
            float bb1 = bias ? bias[c0 + 1] : 0.0f;
            float v0 = acc[mi][ni][0] + bb0;
            float v1 = acc[mi][ni][1] + bb1;
            float v2 = acc[mi][ni][2] + bb0;
            float v3 = acc[mi][ni][3] + bb1;
            if (doRelu) {
                v0 = fmaxf(v0, 0.f); v1 = fmaxf(v1, 0.f);
                v2 = fmaxf(v2, 0.f); v3 = fmaxf(v3, 0.f);
            }
            __half2 p0 = __floats2half2_rn(v0, v1);
            __half2 p1 = __floats2half2_rn(v2, v3);
            *(uint32_t*)(C + (size_t)r0 * Nn + c0) = h2u(p0);
            *(uint32_t*)(C + (size_t)(r0 + 8) * Nn + c0) = h2u(p1);
        }
    }
}

// ---------------- a_s/a_d for layer 0 from g_xh (warp per node) ----------------
__global__ void asd0() {
    int n = blockIdx.x * 8 + (threadIdx.x >> 5);
    int lane = threadIdx.x & 31;
    if (n >= NN) return;
    uint2 u = *(const uint2*)(g_xh + (size_t)n * DD + lane * 4);
    float2 xa = __half22float2(*(__half2*)&u.x);
    float2 xb = __half22float2(*(__half2*)&u.y);
    float r[8];
#pragma unroll
    for (int h = 0; h < 8; h++) {
        const float* w = &g_ws[0][h][lane * 4];
        float p = xa.x * w[0] + xa.y * w[1] + xb.x * w[2] + xb.y * w[3];
#pragma unroll
        for (int o = 16; o; o >>= 1) p += __shfl_xor_sync(0xffffffffu, p, o);
        r[h] = p;
    }
    if (lane < 8) g_asd[0][n * 8 + lane] = r[lane];
}

// fused GAT: staged edge metadata + cooperative weights + gather + softmax + epilogue
__global__ void gat_node(const float* __restrict__ bias, float* __restrict__ outF, int L) {
    int n = blockIdx.x;
    int tid = threadIdx.x;      // 128
    int head = tid >> 5;
    __shared__ float tab_sm[RR * HH];
    __shared__ float s_adn[4];
    __shared__ int   sval[128];
    __shared__ float wbuf[512];
    __shared__ float sbuf[512];
    const float* asd = g_asd[L];
    if (tid < RR * HH) tab_sm[tid] = ((const float*)g_tab)[L * RR * HH + tid];
    if (tid < 4) s_adn[tid] = asd[n * 8 + 4 + tid];
    __syncthreads();

    int p0 = g_off[n], p1 = g_off[n + 1];
    int deg = p1 - p0;
    const uint2* hrow = (const uint2*)g_hHh;
    float4 acc = make_float4(0.f, 0.f, 0.f, 0.f);
    float wsum = 0.0f, tsum = 0.0f;

    for (int base = p0; base < p1; base += 128) {
        int m = min(128, p1 - base);
        // stage metadata + compute all-head weights
        if (tid < m) {
            int v = g_esd[base + tid];
            sval[tid] = v;
            int s = v & 0xFFFFF, t = v >> 20;
            float4 as4 = *(const float4*)(asd + s * 8);
            const float* tb = &tab_sm[t * HH];
            float r0 = as4.x + s_adn[0] + tb[0]; r0 = r0 > 0.f ? r0 : 0.2f * r0;
            float r1 = as4.y + s_adn[1] + tb[1]; r1 = r1 > 0.f ? r1 : 0.2f * r1;
            float r2 = as4.z + s_adn[2] + tb[2]; r2 = r2 > 0.f ? r2 : 0.2f * r2;
            float r3 = as4.w + s_adn[3] + tb[3]; r3 = r3 > 0.f ? r3 : 0.2f * r3;
            float4 w4 = make_float4(__expf(r0), __expf(r1), __expf(r2), __expf(r3));
            *(float4*)&wbuf[tid * 4] = w4;
        }
        __syncthreads();
        // aggregation: 1 LDG per thread per edge
        int e = 0;
        for (; e + 2 <= m; e += 2) {
            int v0 = sval[e], v1 = sval[e + 1];
            int s0 = v0 & 0xFFFFF, s1 = v1 & 0xFFFFF;
            float w0 = wbuf[e * 4 + head];
            float w1 = wbuf[(e + 1) * 4 + head];
            uint2 u0 = hrow[(size_t)s0 * 128 + tid];
            uint2 u1 = hrow[(size_t)s1 * 128 + tid];
            wsum += w0 + w1;
            tsum += tab_sm[(v0 >> 20) * HH + head] + tab_sm[(v1 >> 20) * HH + head];
            float2 f00 = __half22float2(*(__half2*)&u0.x);
            float2 f01 = __half22float2(*(__half2*)&u0.y);
            float2 f10 = __half22float2(*(__half2*)&u1.x);
            float2 f11 = __half22float2(*(__half2*)&u1.y);
            acc.x += w0 * f00.x + w1 * f10.x;
            acc.y += w0 * f00.y + w1 * f10.y;
            acc.z += w0 * f01.x + w1 * f11.x;
            acc.w += w0 * f01.y + w1 * f11.y;
        }
        if (e < m) {
            int v = sval[e];
            int s = v & 0xFFFFF;
            float w = wbuf[e * 4 + head];
            uint2 u = hrow[(size_t)s * 128 + tid];
            wsum += w;
            tsum += tab_sm[(v >> 20) * HH + head];
            float2 f0 = __half22float2(*(__half2*)&u.x);
            float2 f1 = __half22float2(*(__half2*)&u.y);
            acc.x += w * f0.x; acc.y += w * f0.y;
            acc.z += w * f1.x; acc.w += w * f1.y;
        }
        __syncthreads();   // protect sval/wbuf before next chunk
    }
    // self loop
    {
        float asn = asd[n * 8 + head];
        float adn = s_adn[head];
        float sr = asn + adn + tsum / fmaxf((float)deg, 1.0f);
        sr = sr > 0.f ? sr : 0.2f * sr;
        float wself = __expf(sr);
        uint2 u = hrow[(size_t)n * 128 + tid];
        float2 f0 = __half22float2(*(__half2*)&u.x);
        float2 f1 = __half22float2(*(__half2*)&u.y);
        acc.x += wself * f0.x; acc.y += wself * f0.y;
        acc.z += wself * f1.x; acc.w += wself * f1.y;
        float inv = 1.0f / (wsum + wself + 1e-16f);
        acc.x *= inv; acc.y *= inv; acc.z *= inv; acc.w *= inv;
    }
    *(float4*)&sbuf[tid * 4] = acc;
    __syncthreads();
    if (tid < 32) {
        float ov[4];
#pragma unroll
        for (int j = 0; j < 4; j++) {
            int d = tid * 4 + j;
            float v = 0.25f * (sbuf[d] + sbuf[128 + d] + sbuf[256 + d] + sbuf[384 + d]) + bias[d];
            v = fmaxf(v, 0.0f);
            ov[j] = v;
        }
        if (L == 0) {
            __half2 p0 = __floats2half2_rn(ov[0], ov[1]);
            __half2 p1 = __floats2half2_rn(ov[2], ov[3]);
            uint2 pk = make_uint2(h2u(p0), h2u(p1));
            *(uint2*)(g_xh + (size_t)n * DD + tid * 4) = pk;
            float r[8];
#pragma unroll
            for (int h = 0; h < 8; h++) {
                const float* w = &g_ws[1][h][tid * 4];
                float pp = ov[0] * w[0] + ov[1] * w[1] + ov[2] * w[2] + ov[3] * w[3];
#pragma unroll
                for (int o = 16; o; o >>= 1) pp += __shfl_xor_sync(0xffffffffu, pp, o);
                r[h] = pp;
            }
            if (tid < 8) g_asd[1][n * 8 + tid] = r[tid];
        } else {
#pragma unroll
            for (int j = 0; j < 4; j++)
                outF[(size_t)n * DD + tid * 4 + j] = ov[j];
        }
    }
}

// ---------------- host ----------------
template <typename T>
static T* symaddr(const void* s) {
    void* p = nullptr;
    cudaGetSymbolAddress(&p, s);
    return (T*)p;
}

extern "C" void kernel_launch(void* const* d_in, const int* in_sizes, int n_in,
                              void* d_out, int out_size) {
    const float* x   = (const float*)d_in[0];
    const int*   ei  = (const int*)d_in[1];
    const int*   et  = (const int*)d_in[2];
    const float* w1  = (const float*)d_in[3];
    const float* b1  = (const float*)d_in[4];
    const float* w2  = (const float*)d_in[5];
    const float* b2  = (const float*)d_in[6];
    const float* rel = (const float*)d_in[7];
    const float* lin[2]  = {(const float*)d_in[8],  (const float*)d_in[14]};
    const float* line[2] = {(const float*)d_in[9],  (const float*)d_in[15]};
    const float* atts[2] = {(const float*)d_in[10], (const float*)d_in[16]};
    const float* attd[2] = {(const float*)d_in[11], (const float*)d_in[17]};
    const float* atte[2] = {(const float*)d_in[12], (const float*)d_in[18]};
    const float* bias[2] = {(const float*)d_in[13], (const float*)d_in[19]};
    const int* srcp = ei;
    const int* dstp = ei + EE;

    __half* pxp  = symaddr<__half>(g_xp);
    __half* ph1  = symaddr<__half>(g_h1h);
    __half* pxh  = symaddr<__half>(g_xh);
    __half* phH  = symaddr<__half>(g_hHh);
    __half* pw1  = symaddr<__half>(g_w1h);
    __half* pw2  = symaddr<__half>(g_w2h);
    __half* pl0  = symaddr<__half>(g_linh);
    __half* pl1  = pl0 + (size_t)DD * HH * DD;

    cudaFuncSetAttribute(mma_gemm, cudaFuncAttributeMaxDynamicSharedMemorySize, SMEM_SZ);

    setup<<<PADB + ZERB + 1 + 8 + C1B + C2B + C3B, 256>>>(
        x, rel, line[0], atte[0], line[1], atte[1],
        lin[0], atts[0], attd[0], lin[1], atts[1], attd[1], w1, w2);
    count_deg<<<(EE + 255) / 256, 256>>>(dstp);
    scan_lookback<<<SCANB, 128>>>();
    mma_gemm<<<dim3(HID / 128, NPAD / 128), 256, SMEM_SZ>>>(pxp, pw1, b1, ph1, KP1, HID, 1);
    scatter_csr<<<(EE + 255) / 256, 256>>>(srcp, dstp, et);
    mma_gemm<<<dim3(DD / 128, NPAD / 128), 256, SMEM_SZ>>>(ph1, pw2, b2, pxh, HID, DD, 0);
    asd0<<<(NN + 7) / 8, 256>>>();

    for (int L = 0; L < 2; L++) {
        mma_gemm<<<dim3((HH * DD) / 128, NPAD / 128), 256, SMEM_SZ>>>(
            pxh, L ? pl1 : pl0, nullptr, phH, DD, HH * DD, 0);
        gat_node<<<NN, 128>>>(bias[L], (float*)d_out, L);
    }
}